// round 6
// baseline (speedup 1.0000x reference)
#include <cuda_runtime.h>
#include <cuda_bf16.h>
#include <cstdint>

// ---------------- problem constants ----------------
#define NROWS 8000      // B*(T-K) rows of p
#define NCOLS 8176      // B*(T-1)  rows of zn

// ---------------- static scratch ----------------
__device__ float g_h1[8192 * 512];
__device__ float g_h2[8192 * 512];
__device__ float g_xi[8192 * 1536];
__device__ float g_ph[8000 * 512];
__device__ float g_p [8000 * 256];
__device__ float g_zn[8176 * 256];
__device__ float g_hbuf[2][8192];
__device__ float g_E[8000];
__device__ float g_low [8000 * 11];
__device__ float g_high[8000 * 11];
__device__ float g_diag[8000 * 12];
__device__ unsigned g_flags[128 * 8];   // sector-padded per-CTA barrier flags

// ---------------- scoped sync helpers ----------------
__device__ __forceinline__ unsigned ld_acquire_gpu(const unsigned* p) {
    unsigned v;
    asm volatile("ld.acquire.gpu.u32 %0, [%1];" : "=r"(v) : "l"(p) : "memory");
    return v;
}
__device__ __forceinline__ void st_release_gpu(unsigned* p, unsigned v) {
    asm volatile("st.release.gpu.u32 [%0], %1;" :: "l"(p), "r"(v) : "memory");
}
__device__ __forceinline__ void stcg(float* p, float v) {
    asm volatile("st.global.cg.f32 [%0], %1;" :: "l"(p), "f"(v) : "memory");
}
__device__ __forceinline__ void ffma2(unsigned long long& d, unsigned long long a, unsigned long long b) {
    asm("fma.rn.f32x2 %0, %1, %2, %0;" : "+l"(d) : "l"(a), "l"(b));
}

// ---------------- reset ----------------
__global__ void reset_kernel() {
    int idx = blockIdx.x * blockDim.x + threadIdx.x;
    int stride = gridDim.x * blockDim.x;
    for (int i = idx; i < 8000; i += stride) g_E[i] = 0.f;
    for (int i = idx; i < 8000 * 11; i += stride) { g_low[i] = 0.f; g_high[i] = 0.f; }
    for (int i = idx; i < 2 * 8192; i += stride) ((float*)g_hbuf)[i] = 0.f;
    for (int i = idx; i < 128 * 8; i += stride) g_flags[i] = 0u;
}

// ---------------- fp32 SIMT SGEMM (enc chain + xi: bit-accuracy of z,c) ----------
__global__ __launch_bounds__(256) void sgemm128(
    const float* __restrict__ A, const float* __restrict__ W,
    const float* __restrict__ bias, float* __restrict__ C,
    int M, int N, int K, int doRelu, int rowmap)
{
    __shared__ float As[8][128];
    __shared__ float Bs[8][132];
    int tid = threadIdx.x;
    int bx = blockIdx.x, by = blockIdx.y;
    int tx = tid & 15, ty = tid >> 4;

    int arow = tid >> 1;
    int acol = (tid & 1) << 2;
    int grow = by * 128 + arow;
    bool aval = grow < M;
    long ar = grow;
    if (rowmap && aval) ar = grow + (grow / 500) * 12;
    const float* Ap = A + (size_t)ar * K + acol;

    int brow = tid >> 5;
    int bcol = (tid & 31) << 2;
    const float* Bp = W + (size_t)brow * N + (size_t)bx * 128 + bcol;

    float acc[8][8];
#pragma unroll
    for (int i = 0; i < 8; i++)
#pragma unroll
        for (int j = 0; j < 8; j++) acc[i][j] = 0.f;

    for (int k0 = 0; k0 < K; k0 += 8) {
        float4 av = aval ? *(const float4*)(Ap + k0) : make_float4(0.f,0.f,0.f,0.f);
        float4 bv = *(const float4*)(Bp + (size_t)k0 * N);
        As[acol + 0][arow] = av.x; As[acol + 1][arow] = av.y;
        As[acol + 2][arow] = av.z; As[acol + 3][arow] = av.w;
        *(float4*)&Bs[brow][bcol] = bv;
        __syncthreads();
#pragma unroll
        for (int kk = 0; kk < 8; kk++) {
            float a[8], b[8];
            *(float4*)&a[0] = *(const float4*)&As[kk][ty * 8];
            *(float4*)&a[4] = *(const float4*)&As[kk][ty * 8 + 4];
            *(float4*)&b[0] = *(const float4*)&Bs[kk][tx * 8];
            *(float4*)&b[4] = *(const float4*)&Bs[kk][tx * 8 + 4];
#pragma unroll
            for (int i = 0; i < 8; i++)
#pragma unroll
                for (int j = 0; j < 8; j++) acc[i][j] = fmaf(a[i], b[j], acc[i][j]);
        }
        __syncthreads();
    }

    int cbase = bx * 128 + tx * 8;
#pragma unroll
    for (int i = 0; i < 8; i++) {
        int r = by * 128 + ty * 8 + i;
        if (r >= M) continue;
        float* Cp = C + (size_t)r * N + cbase;
#pragma unroll
        for (int j = 0; j < 8; j++) {
            float v = acc[i][j] + bias[cbase + j];
            if (doRelu) v = fmaxf(v, 0.f);
            Cp[j] = v;
        }
    }
}

// ---------------- tf32 helpers ----------------
__device__ __forceinline__ uint32_t f2tf32(float v) {
    uint32_t r;
    asm("cvt.rna.tf32.f32 %0, %1;" : "=r"(r) : "f"(v));
    return r;
}
__device__ __forceinline__ void mma_tf32(
    float& c0, float& c1, float& c2, float& c3,
    uint32_t a0, uint32_t a1, uint32_t a2, uint32_t a3,
    uint32_t b0, uint32_t b1)
{
    asm volatile(
        "mma.sync.aligned.m16n8k8.row.col.f32.tf32.tf32.f32 "
        "{%0,%1,%2,%3}, {%4,%5,%6,%7}, {%8,%9}, {%0,%1,%2,%3};"
        : "+f"(c0), "+f"(c1), "+f"(c2), "+f"(c3)
        : "r"(a0), "r"(a1), "r"(a2), "r"(a3), "r"(b0), "r"(b1));
}

// ---------------- tf32 tensor GEMM (loss-only path) ----------------
#define SA 36
#define SB 37
template<int BMODE, int EPI>
__global__ __launch_bounds__(256) void tmma_kernel(
    const float* __restrict__ A, const float* __restrict__ B,
    const float* __restrict__ bias, float* __restrict__ C,
    int M, int N, int K, int doRelu, int rowmap)
{
    __shared__ uint32_t As[128 * SA];
    __shared__ uint32_t Bs[128 * SB];
    __shared__ float red[128];

    int tid = threadIdx.x;
    int bx = blockIdx.x, by = blockIdx.y;
    int wid = tid >> 5, lane = tid & 31;
    int wm = wid >> 1, wn = wid & 1;
    int g = lane >> 2, tg = lane & 3;

    if (EPI == 1 && tid < 128) red[tid] = 0.f;

    int arow = tid >> 1;
    int akh = (tid & 1) << 4;
    int agrow = by * 128 + arow;
    bool aval = agrow < M;
    long ar = agrow;
    if (rowmap && aval) ar = agrow + (agrow / 500) * 12;
    const float* Ap = A + (size_t)ar * K + akh;

    int bn_d = tid >> 1;
    int bkh_d = (tid & 1) << 4;
    int bgn_d = bx * 128 + bn_d;
    const float* Bp_d = B + (size_t)bgn_d * K + bkh_d;
    int bn_t = tid & 127;
    int bkh_t = (tid >> 7) << 4;
    const float* Bp_t = B + (size_t)(bx * 128 + bn_t);

    float acc[2][8][4];
#pragma unroll
    for (int mi = 0; mi < 2; mi++)
#pragma unroll
        for (int ni = 0; ni < 8; ni++)
#pragma unroll
            for (int q = 0; q < 4; q++) acc[mi][ni][q] = 0.f;

    for (int k0 = 0; k0 < K; k0 += 32) {
#pragma unroll
        for (int i = 0; i < 4; i++) {
            float4 v = aval ? *(const float4*)(Ap + k0 + i * 4)
                            : make_float4(0.f,0.f,0.f,0.f);
            uint32_t* d = &As[arow * SA + akh + i * 4];
            d[0] = f2tf32(v.x); d[1] = f2tf32(v.y);
            d[2] = f2tf32(v.z); d[3] = f2tf32(v.w);
        }
        if (BMODE == 1) {
            bool bv = bgn_d < N;
#pragma unroll
            for (int i = 0; i < 4; i++) {
                float4 v = bv ? *(const float4*)(Bp_d + k0 + i * 4)
                              : make_float4(0.f,0.f,0.f,0.f);
                uint32_t* d = &Bs[bn_d * SB + bkh_d + i * 4];
                d[0] = f2tf32(v.x); d[1] = f2tf32(v.y);
                d[2] = f2tf32(v.z); d[3] = f2tf32(v.w);
            }
        } else {
#pragma unroll
            for (int j = 0; j < 16; j++) {
                int k = bkh_t + j;
                float v = Bp_t[(size_t)(k0 + k) * N];
                Bs[bn_t * SB + k] = f2tf32(v);
            }
        }
        __syncthreads();

#pragma unroll
        for (int ks = 0; ks < 4; ks++) {
            int kb = ks * 8;
            uint32_t a[2][4];
#pragma unroll
            for (int mi = 0; mi < 2; mi++) {
                int r = wm * 32 + mi * 16;
                a[mi][0] = As[(r + g    ) * SA + kb + tg];
                a[mi][1] = As[(r + g + 8) * SA + kb + tg];
                a[mi][2] = As[(r + g    ) * SA + kb + tg + 4];
                a[mi][3] = As[(r + g + 8) * SA + kb + tg + 4];
            }
#pragma unroll
            for (int ni = 0; ni < 8; ni++) {
                int n = wn * 64 + ni * 8;
                uint32_t b0 = Bs[(n + g) * SB + kb + tg];
                uint32_t b1 = Bs[(n + g) * SB + kb + tg + 4];
#pragma unroll
                for (int mi = 0; mi < 2; mi++)
                    mma_tf32(acc[mi][ni][0], acc[mi][ni][1],
                             acc[mi][ni][2], acc[mi][ni][3],
                             a[mi][0], a[mi][1], a[mi][2], a[mi][3], b0, b1);
            }
        }
        __syncthreads();
    }

    if (EPI == 0) {
#pragma unroll
        for (int mi = 0; mi < 2; mi++) {
            int r0 = by * 128 + wm * 32 + mi * 16 + g;
#pragma unroll
            for (int ni = 0; ni < 8; ni++) {
                int cg = bx * 128 + wn * 64 + ni * 8 + tg * 2;
                float b0v = bias[cg], b1v = bias[cg + 1];
                float v0 = acc[mi][ni][0] + b0v;
                float v1 = acc[mi][ni][1] + b1v;
                float v2 = acc[mi][ni][2] + b0v;
                float v3 = acc[mi][ni][3] + b1v;
                if (doRelu) {
                    v0 = fmaxf(v0, 0.f); v1 = fmaxf(v1, 0.f);
                    v2 = fmaxf(v2, 0.f); v3 = fmaxf(v3, 0.f);
                }
                if (r0 < M)     *(float2*)&C[(size_t)r0 * N + cg]       = make_float2(v0, v1);
                if (r0 + 8 < M) *(float2*)&C[(size_t)(r0 + 8) * N + cg] = make_float2(v2, v3);
            }
        }
    } else {
        float rsum[2][2] = {{0.f,0.f},{0.f,0.f}};
#pragma unroll
        for (int ni = 0; ni < 8; ni++) {
            int cg0 = bx * 128 + wn * 64 + ni * 8 + tg * 2;
#pragma unroll
            for (int half = 0; half < 2; half++) {
                int cg = cg0 + half;
                if (cg >= NCOLS) continue;
                int cb = cg / 511;
                int mm = cg - cb * 511;
#pragma unroll
                for (int mi = 0; mi < 2; mi++) {
#pragma unroll
                    for (int rh = 0; rh < 2; rh++) {
                        int rg = by * 128 + wm * 32 + mi * 16 + rh * 8 + g;
                        if (rg >= NROWS) continue;
                        float s = acc[mi][ni][rh * 2 + half];
                        float e = __expf(s - 10.0f);
                        rsum[mi][rh] += e;
                        if (mm < 11) atomicAdd(&g_low[rg * 11 + mm], e);
                        else if (mm >= 500) atomicAdd(&g_high[rg * 11 + mm - 500], e);
                        int bi = rg / 500;
                        if (cb == bi) {
                            int dd = mm - (rg - bi * 500);
                            if (dd >= 0 && dd < 12) g_diag[rg * 12 + dd] = s;
                        }
                    }
                }
            }
        }
#pragma unroll
        for (int mi = 0; mi < 2; mi++)
#pragma unroll
            for (int rh = 0; rh < 2; rh++) {
                float v = rsum[mi][rh];
                v += __shfl_xor_sync(0xffffffffu, v, 1);
                v += __shfl_xor_sync(0xffffffffu, v, 2);
                if (tg == 0)
                    atomicAdd(&red[wm * 32 + mi * 16 + rh * 8 + g], v);
            }
        __syncthreads();
        if (tid < 128) {
            int rr = by * 128 + tid;
            if (rr < NROWS && red[tid] != 0.f) atomicAdd(&g_E[rr], red[tid]);
        }
    }
}

// ---------------- GRU persistent kernel v3 ----------------
// Changes vs v2:
//  * flags barrier: per-CTA st.release to distinct sector-padded flag +
//    128-thread parallel ld.acquire poll  (kills the 128-way same-address
//    L2 RMW serialization ~3.5K cyc/step of the counter barrier)
//  * inner product in fma.rn.f32x2: 12 gate accs packed as 6 f32x2
//    (16 -> 11 instr per k)
__global__ __launch_bounds__(256) void gru_kernel(
    const float* __restrict__ wh, const float* __restrict__ bhn,
    float* __restrict__ cOut)
{
    __shared__ float w_s[512 * 12];     // [k][gate*4 + cc], 16B aligned rows (48B stride)
    __shared__ float red[192 * 17];
    __shared__ float dot_s[192];
    __shared__ float bhn_s[4];
    int tid = threadIdx.x;
    int colBase = blockIdx.x * 4;

    for (int e = tid; e < 6144; e += 256) {
        int k = e / 12, r = e - k * 12;
        int g = r >> 2, cc = r & 3;
        w_s[e] = wh[(size_t)k * 1536 + g * 512 + colBase + cc];
    }
    if (tid < 4) bhn_s[tid] = bhn[colBase + tid];
    __syncthreads();

    int ks = tid >> 4;          // 0..15, owns k in [ks*32, ks*32+32)
    int row = tid & 15;         // batch
    int kbase = ks * 32;
    int grow2 = tid >> 2;       // gate thread: batch row (tid<64)
    int gcol = colBase + (tid & 3);

    for (int t = 0; t < 512; t++) {
        int rb = t & 1;
        const float* hb = g_hbuf[rb];

        float xr = 0.f, xu = 0.f, xn = 0.f, hold = 0.f;
        if (tid < 64) {
            size_t base = ((size_t)(grow2 << 9) + t) * 1536 + gcol;
            xr = __ldg(&g_xi[base]);
            xu = __ldg(&g_xi[base + 512]);
            xn = __ldg(&g_xi[base + 1024]);
            hold = __ldcg(&hb[gcol * 16 + grow2]);
        }

        unsigned long long acc2[6];
#pragma unroll
        for (int q = 0; q < 6; q++) acc2[q] = 0ull;
#pragma unroll 8
        for (int j = 0; j < 32; j++) {
            int k = kbase + j;
            float hv = __ldcg(&hb[k * 16 + row]);
            unsigned long long hh;
            asm("mov.b64 %0, {%1, %1};" : "=l"(hh) : "r"(__float_as_uint(hv)));
            const unsigned long long* w2 = (const unsigned long long*)&w_s[k * 12];
            ffma2(acc2[0], w2[0], hh);
            ffma2(acc2[1], w2[1], hh);
            ffma2(acc2[2], w2[2], hh);
            ffma2(acc2[3], w2[3], hh);
            ffma2(acc2[4], w2[4], hh);
            ffma2(acc2[5], w2[5], hh);
        }
#pragma unroll
        for (int q = 0; q < 6; q++) {
            unsigned lo, hi;
            asm("mov.b64 {%0, %1}, %2;" : "=r"(lo), "=r"(hi) : "l"(acc2[q]));
            red[(row * 12 + 2 * q    ) * 17 + ks] = __uint_as_float(lo);
            red[(row * 12 + 2 * q + 1) * 17 + ks] = __uint_as_float(hi);
        }
        __syncthreads();

        if (tid < 192) {
            float v = 0.f;
#pragma unroll
            for (int s = 0; s < 16; s++) v += red[tid * 17 + s];
            dot_s[tid] = v;
        }
        __syncthreads();

        if (tid < 64) {
            int cc = tid & 3;
            float hr = dot_s[grow2 * 12 + cc];
            float hu = dot_s[grow2 * 12 + 4 + cc];
            float hn = dot_s[grow2 * 12 + 8 + cc];
            float r = 1.f / (1.f + __expf(-(xr + hr)));
            float u = 1.f / (1.f + __expf(-(xu + hu)));
            float n = tanhf(xn + r * (hn + bhn_s[cc]));
            float hnew = (1.f - u) * n + u * hold;
            stcg(&g_hbuf[rb ^ 1][gcol * 16 + grow2], hnew);
            cOut[((size_t)(grow2 << 9) + t) * 512 + gcol] = hnew;
        }

        __syncthreads();   // all h stores of this CTA precede the release
        if (tid == 0) st_release_gpu(&g_flags[blockIdx.x * 8], (unsigned)(t + 1));
        if (tid < 128) {
            unsigned tgt = (unsigned)(t + 1);
            while (ld_acquire_gpu(&g_flags[tid * 8]) < tgt) { }
        }
        __syncthreads();   // acquires propagate to all threads (cta-scope bar)
    }
}

// ---------------- row L2-normalize ----------------
__device__ __forceinline__ void norm_row(const float* src, float* dst, int lane, float extraScale) {
    float4 a = ((const float4*)src)[lane];
    float4 b = ((const float4*)src)[lane + 32];
    float ss = a.x*a.x + a.y*a.y + a.z*a.z + a.w*a.w
             + b.x*b.x + b.y*b.y + b.z*b.z + b.w*b.w;
#pragma unroll
    for (int o = 16; o > 0; o >>= 1) ss += __shfl_xor_sync(0xffffffffu, ss, o);
    float r = rsqrtf(ss);
    r = r * (1.5f - 0.5f * ss * r * r);
    r *= extraScale;
    a.x*=r; a.y*=r; a.z*=r; a.w*=r; b.x*=r; b.y*=r; b.z*=r; b.w*=r;
    ((float4*)dst)[lane] = a;
    ((float4*)dst)[lane + 32] = b;
}

__global__ void norm_p_kernel() {
    int w = (blockIdx.x * blockDim.x + threadIdx.x) >> 5;
    if (w >= NROWS) return;
    norm_row(g_p + (size_t)w * 256, g_p + (size_t)w * 256, threadIdx.x & 31, 10.0f);
}

__global__ void build_zn_kernel(const float* __restrict__ z) {
    int w = (blockIdx.x * blockDim.x + threadIdx.x) >> 5;
    if (w >= NCOLS) return;
    int b = w / 511, tt = w % 511;
    const float* src = z + (size_t)(b * 512 + tt + 1) * 256;
    norm_row(src, g_zn + (size_t)w * 256, threadIdx.x & 31, 1.0f);
}

// ---------------- loss finisher ----------------
__global__ void loss_kernel(float* __restrict__ out) {
    __shared__ float part[1024];
    int tid = threadIdx.x;
    float tot = 0.f;
    for (int i = tid; i < NROWS; i += 1024) {
        float E = g_E[i];
        float L[11], H[11];
        float low = 0.f, high = 0.f;
#pragma unroll
        for (int j = 0; j < 11; j++) {
            L[j] = g_low[i * 11 + j];
            H[j] = g_high[i * 11 + j];
            high += H[j];
        }
#pragma unroll
        for (int k = 1; k <= 12; k++) {
            if (k >= 2) { low += L[k - 2]; high -= H[k - 2]; }
            float window = E - low - high;
            tot += g_diag[i * 12 + (k - 1)] - (10.0f + logf(window));
        }
    }
    part[tid] = tot;
    __syncthreads();
    for (int s = 512; s > 0; s >>= 1) {
        if (tid < s) part[tid] += part[tid + s];
        __syncthreads();
    }
    if (tid == 0) out[0] = -part[0] / (12.0f * (float)NROWS);
}

// ---------------- driver ----------------
extern "C" void kernel_launch(void* const* d_in, const int* in_sizes, int n_in,
                              void* d_out, int out_size) {
    const float* x       = (const float*)d_in[0];
    const float* enc_w1  = (const float*)d_in[1];
    const float* enc_b1  = (const float*)d_in[2];
    const float* enc_w2  = (const float*)d_in[3];
    const float* enc_b2  = (const float*)d_in[4];
    const float* enc_w3  = (const float*)d_in[5];
    const float* enc_b3  = (const float*)d_in[6];
    const float* gru_wi  = (const float*)d_in[7];
    const float* gru_bi  = (const float*)d_in[8];
    const float* gru_wh  = (const float*)d_in[9];
    const float* gru_bhn = (const float*)d_in[10];
    const float* pred_w1 = (const float*)d_in[11];
    const float* pred_b1 = (const float*)d_in[12];
    const float* pred_w2 = (const float*)d_in[13];
    const float* pred_b2 = (const float*)d_in[14];

    float* out  = (float*)d_out;
    float* zOut = out;                       // [8192, 256]
    float* cOut = out + 2097152;             // [8192, 512]
    float* lOut = out + (out_size - 1);

    // Resolve true device addresses of scratch symbols (host-shadow trap!)
    float *h1, *h2, *xi, *ph, *p, *zn;
    cudaGetSymbolAddress((void**)&h1, g_h1);
    cudaGetSymbolAddress((void**)&h2, g_h2);
    cudaGetSymbolAddress((void**)&xi, g_xi);
    cudaGetSymbolAddress((void**)&ph, g_ph);
    cudaGetSymbolAddress((void**)&p,  g_p);
    cudaGetSymbolAddress((void**)&zn, g_zn);

    reset_kernel<<<64, 256>>>();

    dim3 t256(256);
    // encoder (fp32 — z exactness)
    sgemm128<<<dim3(4, 64),  t256>>>(x,    enc_w1, enc_b1, h1,   8192, 512,  128, 1, 0);
    sgemm128<<<dim3(4, 64),  t256>>>(h1,   enc_w2, enc_b2, h2,   8192, 512,  512, 1, 0);
    sgemm128<<<dim3(2, 64),  t256>>>(h2,   enc_w3, enc_b3, zOut, 8192, 256,  512, 0, 0);
    // GRU input projection (fp32 — c accuracy)
    sgemm128<<<dim3(12, 64), t256>>>(zOut, gru_wi, gru_bi, xi,   8192, 1536, 256, 0, 0);
    // GRU recurrence (v3: flags barrier + f32x2)
    gru_kernel<<<128, 256>>>(gru_wh, gru_bhn, cOut);
    // prediction net on c[:, :-12] — tf32 tensor cores (loss-only path)
    tmma_kernel<0,0><<<dim3(4, 63), t256>>>(cOut, pred_w1, pred_b1, ph, 8000, 512, 512, 1, 1);
    tmma_kernel<0,0><<<dim3(2, 63), t256>>>(ph,   pred_w2, pred_b2, p,  8000, 256, 512, 0, 0);
    // normalize
    norm_p_kernel<<<1000, 256>>>();
    build_zn_kernel<<<1022, 256>>>(zOut);
    // fused Gram + epilogue — tf32 tensor cores
    tmma_kernel<1,1><<<dim3(64, 63), t256>>>(p, zn, nullptr, nullptr, NROWS, NCOLS, 256, 0, 0);
    // loss
    loss_kernel<<<1, 1024>>>(lOut);
}

// round 7
// speedup vs baseline: 1.2255x; 1.2255x over previous
#include <cuda_runtime.h>
#include <cuda_bf16.h>
#include <cstdint>

// ---------------- problem constants ----------------
#define NROWS 8000      // B*(T-K) rows of p
#define NCOLS 8176      // B*(T-1)  rows of zn

// ---------------- static scratch ----------------
__device__ float g_h1[8192 * 512];
__device__ float g_h2[8192 * 512];
__device__ float g_xi[8192 * 1536];
__device__ float g_ph[8000 * 512];
__device__ float g_p [8000 * 256];
__device__ float g_zn[8176 * 256];
__device__ float g_hbuf[2][8192];
__device__ float g_E[8000];
__device__ float g_low [8000 * 11];
__device__ float g_high[8000 * 11];
__device__ float g_diag[8000 * 12];
__device__ unsigned g_bar;

// ---------------- scoped sync helpers ----------------
__device__ __forceinline__ unsigned ld_acquire_gpu(const unsigned* p) {
    unsigned v;
    asm volatile("ld.acquire.gpu.u32 %0, [%1];" : "=r"(v) : "l"(p) : "memory");
    return v;
}
__device__ __forceinline__ void red_release_gpu(unsigned* p, unsigned v) {
    asm volatile("red.release.gpu.add.u32 [%0], %1;" :: "l"(p), "r"(v) : "memory");
}
__device__ __forceinline__ void stcg(float* p, float v) {
    asm volatile("st.global.cg.f32 [%0], %1;" :: "l"(p), "f"(v) : "memory");
}

// ---------------- reset ----------------
__global__ void reset_kernel() {
    int idx = blockIdx.x * blockDim.x + threadIdx.x;
    int stride = gridDim.x * blockDim.x;
    for (int i = idx; i < 8000; i += stride) g_E[i] = 0.f;
    for (int i = idx; i < 8000 * 11; i += stride) { g_low[i] = 0.f; g_high[i] = 0.f; }
    for (int i = idx; i < 2 * 8192; i += stride) ((float*)g_hbuf)[i] = 0.f;
    if (idx == 0) g_bar = 0u;
}

// ---------------- fp32 SIMT SGEMM, double-buffered (enc chain + xi) ----------
// 128x128 tile, BK=8, 256 threads, 8x8/thread. ONE sync per k-tile; next
// tile's gmem loads overlap current tile's FMAs.
__global__ __launch_bounds__(256) void sgemm128(
    const float* __restrict__ A, const float* __restrict__ W,
    const float* __restrict__ bias, float* __restrict__ C,
    int M, int N, int K, int doRelu, int rowmap)
{
    __shared__ float As[2][8][128];
    __shared__ float Bs[2][8][132];
    int tid = threadIdx.x;
    int bx = blockIdx.x, by = blockIdx.y;
    int tx = tid & 15, ty = tid >> 4;

    int arow = tid >> 1;
    int acol = (tid & 1) << 2;
    int grow = by * 128 + arow;
    bool aval = grow < M;
    long ar = grow;
    if (rowmap && aval) ar = grow + (grow / 500) * 12;
    const float* Ap = A + (size_t)ar * K + acol;

    int brow = tid >> 5;
    int bcol = (tid & 31) << 2;
    const float* Bp = W + (size_t)brow * N + (size_t)bx * 128 + bcol;

    float acc[8][8];
#pragma unroll
    for (int i = 0; i < 8; i++)
#pragma unroll
        for (int j = 0; j < 8; j++) acc[i][j] = 0.f;

    int tiles = K >> 3;
    // preload tile 0
    {
        float4 av = aval ? *(const float4*)(Ap) : make_float4(0.f,0.f,0.f,0.f);
        float4 bv = *(const float4*)(Bp);
        As[0][acol + 0][arow] = av.x; As[0][acol + 1][arow] = av.y;
        As[0][acol + 2][arow] = av.z; As[0][acol + 3][arow] = av.w;
        *(float4*)&Bs[0][brow][bcol] = bv;
    }
    __syncthreads();

    for (int t = 0; t < tiles; t++) {
        int cur = t & 1;
        bool more = (t + 1) < tiles;
        float4 av2, bv2;
        if (more) {
            int k0 = (t + 1) << 3;
            av2 = aval ? *(const float4*)(Ap + k0) : make_float4(0.f,0.f,0.f,0.f);
            bv2 = *(const float4*)(Bp + (size_t)k0 * N);
        }
#pragma unroll
        for (int kk = 0; kk < 8; kk++) {
            float a[8], b[8];
            *(float4*)&a[0] = *(const float4*)&As[cur][kk][ty * 8];
            *(float4*)&a[4] = *(const float4*)&As[cur][kk][ty * 8 + 4];
            *(float4*)&b[0] = *(const float4*)&Bs[cur][kk][tx * 8];
            *(float4*)&b[4] = *(const float4*)&Bs[cur][kk][tx * 8 + 4];
#pragma unroll
            for (int i = 0; i < 8; i++)
#pragma unroll
                for (int j = 0; j < 8; j++) acc[i][j] = fmaf(a[i], b[j], acc[i][j]);
        }
        if (more) {
            int nxt = cur ^ 1;
            As[nxt][acol + 0][arow] = av2.x; As[nxt][acol + 1][arow] = av2.y;
            As[nxt][acol + 2][arow] = av2.z; As[nxt][acol + 3][arow] = av2.w;
            *(float4*)&Bs[nxt][brow][bcol] = bv2;
        }
        __syncthreads();
    }

    int cbase = bx * 128 + tx * 8;
#pragma unroll
    for (int i = 0; i < 8; i++) {
        int r = by * 128 + ty * 8 + i;
        if (r >= M) continue;
        float* Cp = C + (size_t)r * N + cbase;
#pragma unroll
        for (int j = 0; j < 8; j++) {
            float v = acc[i][j] + bias[cbase + j];
            if (doRelu) v = fmaxf(v, 0.f);
            Cp[j] = v;
        }
    }
}

// ---------------- tf32 helpers ----------------
__device__ __forceinline__ uint32_t f2tf32(float v) {
    uint32_t r;
    asm("cvt.rna.tf32.f32 %0, %1;" : "=r"(r) : "f"(v));
    return r;
}
__device__ __forceinline__ void mma_tf32(
    float& c0, float& c1, float& c2, float& c3,
    uint32_t a0, uint32_t a1, uint32_t a2, uint32_t a3,
    uint32_t b0, uint32_t b1)
{
    asm volatile(
        "mma.sync.aligned.m16n8k8.row.col.f32.tf32.tf32.f32 "
        "{%0,%1,%2,%3}, {%4,%5,%6,%7}, {%8,%9}, {%0,%1,%2,%3};"
        : "+f"(c0), "+f"(c1), "+f"(c2), "+f"(c3)
        : "r"(a0), "r"(a1), "r"(a2), "r"(a3), "r"(b0), "r"(b1));
}

// ---------------- tf32 tensor GEMM, double-buffered (loss-only path) --------
// CTA tile 128x128, BK=16, 8 warps (4m x 2n), one sync per tile.
// Stride 20 layout: fragment banks (20g+tg)%32 cover all 32 -> conflict-free.
#define S2 20
template<int BMODE, int EPI>
__global__ __launch_bounds__(256) void tmma_kernel(
    const float* __restrict__ A, const float* __restrict__ B,
    const float* __restrict__ bias, float* __restrict__ C,
    int M, int N, int K, int doRelu, int rowmap)
{
    __shared__ uint32_t As[2][128 * S2];
    __shared__ uint32_t Bs[2][128 * S2];
    __shared__ float red[128];

    int tid = threadIdx.x;
    int bx = blockIdx.x, by = blockIdx.y;
    int wid = tid >> 5, lane = tid & 31;
    int wm = wid >> 1, wn = wid & 1;
    int g = lane >> 2, tg = lane & 3;

    if (EPI == 1 && tid < 128) red[tid] = 0.f;

    // A: 2 threads/row, 8 k each
    int arow = tid >> 1;
    int akh = (tid & 1) << 3;
    int agrow = by * 128 + arow;
    bool aval = agrow < M;
    long ar = agrow;
    if (rowmap && aval) ar = agrow + (agrow / 500) * 12;
    const float* Ap = A + (size_t)ar * K;

    // B (BMODE 1): [N][K] direct, 2 threads/row
    const float* Bp_d = B + (size_t)(bx * 128 + arow) * K;
    bool bval_d = (bx * 128 + arow) < N;
    // B (BMODE 0): weights [K][N], transpose-load: thread owns col bn_t, 8 ks
    int bn_t = tid & 127;
    int bkh_t = (tid >> 7) << 3;
    const float* Bp_t = B + (size_t)(bx * 128 + bn_t);

    float acc[2][8][4];
#pragma unroll
    for (int mi = 0; mi < 2; mi++)
#pragma unroll
        for (int ni = 0; ni < 8; ni++)
#pragma unroll
            for (int q = 0; q < 4; q++) acc[mi][ni][q] = 0.f;

    int tiles = K >> 4;
    // preload tile 0 directly into smem buf 0
    {
        float4 a0 = aval ? *(const float4*)(Ap + akh)     : make_float4(0.f,0.f,0.f,0.f);
        float4 a1 = aval ? *(const float4*)(Ap + akh + 4) : make_float4(0.f,0.f,0.f,0.f);
        uint32_t* d = &As[0][arow * S2 + akh];
        d[0]=f2tf32(a0.x); d[1]=f2tf32(a0.y); d[2]=f2tf32(a0.z); d[3]=f2tf32(a0.w);
        d[4]=f2tf32(a1.x); d[5]=f2tf32(a1.y); d[6]=f2tf32(a1.z); d[7]=f2tf32(a1.w);
        if (BMODE == 1) {
            float4 b0 = bval_d ? *(const float4*)(Bp_d + akh)     : make_float4(0.f,0.f,0.f,0.f);
            float4 b1 = bval_d ? *(const float4*)(Bp_d + akh + 4) : make_float4(0.f,0.f,0.f,0.f);
            uint32_t* e = &Bs[0][arow * S2 + akh];
            e[0]=f2tf32(b0.x); e[1]=f2tf32(b0.y); e[2]=f2tf32(b0.z); e[3]=f2tf32(b0.w);
            e[4]=f2tf32(b1.x); e[5]=f2tf32(b1.y); e[6]=f2tf32(b1.z); e[7]=f2tf32(b1.w);
        } else {
#pragma unroll
            for (int j = 0; j < 8; j++)
                Bs[0][bn_t * S2 + bkh_t + j] = f2tf32(Bp_t[(size_t)(bkh_t + j) * N]);
        }
    }
    __syncthreads();

    for (int t = 0; t < tiles; t++) {
        int cur = t & 1;
        bool more = (t + 1) < tiles;
        float4 pa0, pa1, pb0, pb1;
        float pbs[8];
        if (more) {
            int k0 = (t + 1) << 4;
            pa0 = aval ? *(const float4*)(Ap + k0 + akh)     : make_float4(0.f,0.f,0.f,0.f);
            pa1 = aval ? *(const float4*)(Ap + k0 + akh + 4) : make_float4(0.f,0.f,0.f,0.f);
            if (BMODE == 1) {
                pb0 = bval_d ? *(const float4*)(Bp_d + k0 + akh)     : make_float4(0.f,0.f,0.f,0.f);
                pb1 = bval_d ? *(const float4*)(Bp_d + k0 + akh + 4) : make_float4(0.f,0.f,0.f,0.f);
            } else {
#pragma unroll
                for (int j = 0; j < 8; j++)
                    pbs[j] = Bp_t[(size_t)(k0 + bkh_t + j) * N];
            }
        }
        // compute tile t
#pragma unroll
        for (int ks = 0; ks < 2; ks++) {
            int kb = ks * 8;
            uint32_t a[2][4];
#pragma unroll
            for (int mi = 0; mi < 2; mi++) {
                int r = wm * 32 + mi * 16;
                a[mi][0] = As[cur][(r + g    ) * S2 + kb + tg];
                a[mi][1] = As[cur][(r + g + 8) * S2 + kb + tg];
                a[mi][2] = As[cur][(r + g    ) * S2 + kb + tg + 4];
                a[mi][3] = As[cur][(r + g + 8) * S2 + kb + tg + 4];
            }
#pragma unroll
            for (int ni = 0; ni < 8; ni++) {
                int n = wn * 64 + ni * 8;
                uint32_t b0 = Bs[cur][(n + g) * S2 + kb + tg];
                uint32_t b1 = Bs[cur][(n + g) * S2 + kb + tg + 4];
#pragma unroll
                for (int mi = 0; mi < 2; mi++)
                    mma_tf32(acc[mi][ni][0], acc[mi][ni][1],
                             acc[mi][ni][2], acc[mi][ni][3],
                             a[mi][0], a[mi][1], a[mi][2], a[mi][3], b0, b1);
            }
        }
        if (more) {
            int nxt = cur ^ 1;
            uint32_t* d = &As[nxt][arow * S2 + akh];
            d[0]=f2tf32(pa0.x); d[1]=f2tf32(pa0.y); d[2]=f2tf32(pa0.z); d[3]=f2tf32(pa0.w);
            d[4]=f2tf32(pa1.x); d[5]=f2tf32(pa1.y); d[6]=f2tf32(pa1.z); d[7]=f2tf32(pa1.w);
            if (BMODE == 1) {
                uint32_t* e = &Bs[nxt][arow * S2 + akh];
                e[0]=f2tf32(pb0.x); e[1]=f2tf32(pb0.y); e[2]=f2tf32(pb0.z); e[3]=f2tf32(pb0.w);
                e[4]=f2tf32(pb1.x); e[5]=f2tf32(pb1.y); e[6]=f2tf32(pb1.z); e[7]=f2tf32(pb1.w);
            } else {
#pragma unroll
                for (int j = 0; j < 8; j++)
                    Bs[nxt][bn_t * S2 + bkh_t + j] = f2tf32(pbs[j]);
            }
        }
        __syncthreads();
    }

    if (EPI == 0) {
#pragma unroll
        for (int mi = 0; mi < 2; mi++) {
            int r0 = by * 128 + wm * 32 + mi * 16 + g;
#pragma unroll
            for (int ni = 0; ni < 8; ni++) {
                int cg = bx * 128 + wn * 64 + ni * 8 + tg * 2;
                float b0v = bias[cg], b1v = bias[cg + 1];
                float v0 = acc[mi][ni][0] + b0v;
                float v1 = acc[mi][ni][1] + b1v;
                float v2 = acc[mi][ni][2] + b0v;
                float v3 = acc[mi][ni][3] + b1v;
                if (doRelu) {
                    v0 = fmaxf(v0, 0.f); v1 = fmaxf(v1, 0.f);
                    v2 = fmaxf(v2, 0.f); v3 = fmaxf(v3, 0.f);
                }
                if (r0 < M)     *(float2*)&C[(size_t)r0 * N + cg]       = make_float2(v0, v1);
                if (r0 + 8 < M) *(float2*)&C[(size_t)(r0 + 8) * N + cg] = make_float2(v2, v3);
            }
        }
    } else {
        float rsum[2][2] = {{0.f,0.f},{0.f,0.f}};
#pragma unroll
        for (int ni = 0; ni < 8; ni++) {
            int cg0 = bx * 128 + wn * 64 + ni * 8 + tg * 2;
#pragma unroll
            for (int half = 0; half < 2; half++) {
                int cg = cg0 + half;
                if (cg >= NCOLS) continue;
                int cb = cg / 511;
                int mm = cg - cb * 511;
#pragma unroll
                for (int mi = 0; mi < 2; mi++) {
#pragma unroll
                    for (int rh = 0; rh < 2; rh++) {
                        int rg = by * 128 + wm * 32 + mi * 16 + rh * 8 + g;
                        if (rg >= NROWS) continue;
                        float s = acc[mi][ni][rh * 2 + half];
                        float e = __expf(s - 10.0f);
                        rsum[mi][rh] += e;
                        if (mm < 11) atomicAdd(&g_low[rg * 11 + mm], e);
                        else if (mm >= 500) atomicAdd(&g_high[rg * 11 + mm - 500], e);
                        int bi = rg / 500;
                        if (cb == bi) {
                            int dd = mm - (rg - bi * 500);
                            if (dd >= 0 && dd < 12) g_diag[rg * 12 + dd] = s;
                        }
                    }
                }
            }
        }
#pragma unroll
        for (int mi = 0; mi < 2; mi++)
#pragma unroll
            for (int rh = 0; rh < 2; rh++) {
                float v = rsum[mi][rh];
                v += __shfl_xor_sync(0xffffffffu, v, 1);
                v += __shfl_xor_sync(0xffffffffu, v, 2);
                if (tg == 0)
                    atomicAdd(&red[wm * 32 + mi * 16 + rh * 8 + g], v);
            }
        __syncthreads();
        if (tid < 128) {
            int rr = by * 128 + tid;
            if (rr < NROWS && red[tid] != 0.f) atomicAdd(&g_E[rr], red[tid]);
        }
    }
}

// ---------------- GRU persistent kernel (R5-measured version, reverted) -----
// 128 CTAs x 256 threads. Counter barrier (red.release + tid0 acquire-poll);
// w_s [k][12] with float4 loads; h via st.cg/ld.cg.
__global__ __launch_bounds__(256) void gru_kernel(
    const float* __restrict__ wh, const float* __restrict__ bhn,
    float* __restrict__ cOut)
{
    __shared__ float w_s[512 * 12];
    __shared__ float red[192 * 17];
    __shared__ float dot_s[192];
    __shared__ float bhn_s[4];
    int tid = threadIdx.x;
    int colBase = blockIdx.x * 4;

    for (int e = tid; e < 6144; e += 256) {
        int k = e / 12, r = e - k * 12;
        int g = r >> 2, cc = r & 3;
        w_s[e] = wh[(size_t)k * 1536 + g * 512 + colBase + cc];
    }
    if (tid < 4) bhn_s[tid] = bhn[colBase + tid];

    unsigned* barp; { unsigned* t_; asm("mov.u64 %0, g_bar;" : "=l"(t_)); barp = t_; }
    __syncthreads();

    int ks = tid >> 4;
    int row = tid & 15;
    int kbase = ks * 32;
    int grow2 = tid >> 2;
    int gcol = colBase + (tid & 3);

    for (int t = 0; t < 512; t++) {
        int rb = t & 1;
        const float* hb = g_hbuf[rb];

        float xr = 0.f, xu = 0.f, xn = 0.f, hold = 0.f;
        if (tid < 64) {
            size_t base = ((size_t)(grow2 << 9) + t) * 1536 + gcol;
            xr = __ldg(&g_xi[base]);
            xu = __ldg(&g_xi[base + 512]);
            xn = __ldg(&g_xi[base + 1024]);
            hold = __ldcg(&hb[gcol * 16 + grow2]);
        }

        float acc[12];
#pragma unroll
        for (int g = 0; g < 12; g++) acc[g] = 0.f;
#pragma unroll 8
        for (int j = 0; j < 32; j++) {
            int k = kbase + j;
            float hv = __ldcg(&hb[k * 16 + row]);
            const float4* w4 = (const float4*)&w_s[k * 12];
            float4 wr = w4[0], wu = w4[1], wn4 = w4[2];
            acc[0]  = fmaf(wr.x,  hv, acc[0]);
            acc[1]  = fmaf(wr.y,  hv, acc[1]);
            acc[2]  = fmaf(wr.z,  hv, acc[2]);
            acc[3]  = fmaf(wr.w,  hv, acc[3]);
            acc[4]  = fmaf(wu.x,  hv, acc[4]);
            acc[5]  = fmaf(wu.y,  hv, acc[5]);
            acc[6]  = fmaf(wu.z,  hv, acc[6]);
            acc[7]  = fmaf(wu.w,  hv, acc[7]);
            acc[8]  = fmaf(wn4.x, hv, acc[8]);
            acc[9]  = fmaf(wn4.y, hv, acc[9]);
            acc[10] = fmaf(wn4.z, hv, acc[10]);
            acc[11] = fmaf(wn4.w, hv, acc[11]);
        }
#pragma unroll
        for (int g = 0; g < 12; g++) red[(row * 12 + g) * 17 + ks] = acc[g];
        __syncthreads();

        if (tid < 192) {
            float v = 0.f;
#pragma unroll
            for (int s = 0; s < 16; s++) v += red[tid * 17 + s];
            dot_s[tid] = v;
        }
        __syncthreads();

        if (tid < 64) {
            int cc = tid & 3;
            float hr = dot_s[grow2 * 12 + cc];
            float hu = dot_s[grow2 * 12 + 4 + cc];
            float hn = dot_s[grow2 * 12 + 8 + cc];
            float r = 1.f / (1.f + __expf(-(xr + hr)));
            float u = 1.f / (1.f + __expf(-(xu + hu)));
            float n = tanhf(xn + r * (hn + bhn_s[cc]));
            float hnew = (1.f - u) * n + u * hold;
            stcg(&g_hbuf[rb ^ 1][gcol * 16 + grow2], hnew);
            cOut[((size_t)(grow2 << 9) + t) * 512 + gcol] = hnew;
        }

        __syncthreads();
        if (tid == 0) {
            red_release_gpu(barp, 1u);
            unsigned tgt = 128u * (unsigned)(t + 1);
            while (ld_acquire_gpu(barp) < tgt) { }
        }
        __syncthreads();
    }
}

// ---------------- row L2-normalize ----------------
__device__ __forceinline__ void norm_row(const float* src, float* dst, int lane, float extraScale) {
    float4 a = ((const float4*)src)[lane];
    float4 b = ((const float4*)src)[lane + 32];
    float ss = a.x*a.x + a.y*a.y + a.z*a.z + a.w*a.w
             + b.x*b.x + b.y*b.y + b.z*b.z + b.w*b.w;
#pragma unroll
    for (int o = 16; o > 0; o >>= 1) ss += __shfl_xor_sync(0xffffffffu, ss, o);
    float r = rsqrtf(ss);
    r = r * (1.5f - 0.5f * ss * r * r);
    r *= extraScale;
    a.x*=r; a.y*=r; a.z*=r; a.w*=r; b.x*=r; b.y*=r; b.z*=r; b.w*=r;
    ((float4*)dst)[lane] = a;
    ((float4*)dst)[lane + 32] = b;
}

__global__ void norm_p_kernel() {
    int w = (blockIdx.x * blockDim.x + threadIdx.x) >> 5;
    if (w >= NROWS) return;
    norm_row(g_p + (size_t)w * 256, g_p + (size_t)w * 256, threadIdx.x & 31, 10.0f);
}

__global__ void build_zn_kernel(const float* __restrict__ z) {
    int w = (blockIdx.x * blockDim.x + threadIdx.x) >> 5;
    if (w >= NCOLS) return;
    int b = w / 511, tt = w % 511;
    const float* src = z + (size_t)(b * 512 + tt + 1) * 256;
    norm_row(src, g_zn + (size_t)w * 256, threadIdx.x & 31, 1.0f);
}

// ---------------- loss finisher ----------------
__global__ void loss_kernel(float* __restrict__ out) {
    __shared__ float part[1024];
    int tid = threadIdx.x;
    float tot = 0.f;
    for (int i = tid; i < NROWS; i += 1024) {
        float E = g_E[i];
        float L[11], H[11];
        float low = 0.f, high = 0.f;
#pragma unroll
        for (int j = 0; j < 11; j++) {
            L[j] = g_low[i * 11 + j];
            H[j] = g_high[i * 11 + j];
            high += H[j];
        }
#pragma unroll
        for (int k = 1; k <= 12; k++) {
            if (k >= 2) { low += L[k - 2]; high -= H[k - 2]; }
            float window = E - low - high;
            tot += g_diag[i * 12 + (k - 1)] - (10.0f + logf(window));
        }
    }
    part[tid] = tot;
    __syncthreads();
    for (int s = 512; s > 0; s >>= 1) {
        if (tid < s) part[tid] += part[tid + s];
        __syncthreads();
    }
    if (tid == 0) out[0] = -part[0] / (12.0f * (float)NROWS);
}

// ---------------- driver ----------------
extern "C" void kernel_launch(void* const* d_in, const int* in_sizes, int n_in,
                              void* d_out, int out_size) {
    const float* x       = (const float*)d_in[0];
    const float* enc_w1  = (const float*)d_in[1];
    const float* enc_b1  = (const float*)d_in[2];
    const float* enc_w2  = (const float*)d_in[3];
    const float* enc_b2  = (const float*)d_in[4];
    const float* enc_w3  = (const float*)d_in[5];
    const float* enc_b3  = (const float*)d_in[6];
    const float* gru_wi  = (const float*)d_in[7];
    const float* gru_bi  = (const float*)d_in[8];
    const float* gru_wh  = (const float*)d_in[9];
    const float* gru_bhn = (const float*)d_in[10];
    const float* pred_w1 = (const float*)d_in[11];
    const float* pred_b1 = (const float*)d_in[12];
    const float* pred_w2 = (const float*)d_in[13];
    const float* pred_b2 = (const float*)d_in[14];

    float* out  = (float*)d_out;
    float* zOut = out;                       // [8192, 256]
    float* cOut = out + 2097152;             // [8192, 512]
    float* lOut = out + (out_size - 1);

    // Resolve true device addresses of scratch symbols (host-shadow trap!)
    float *h1, *h2, *xi, *ph, *p, *zn;
    cudaGetSymbolAddress((void**)&h1, g_h1);
    cudaGetSymbolAddress((void**)&h2, g_h2);
    cudaGetSymbolAddress((void**)&xi, g_xi);
    cudaGetSymbolAddress((void**)&ph, g_ph);
    cudaGetSymbolAddress((void**)&p,  g_p);
    cudaGetSymbolAddress((void**)&zn, g_zn);

    reset_kernel<<<64, 256>>>();

    dim3 t256(256);
    // encoder (fp32 — z exactness)
    sgemm128<<<dim3(4, 64),  t256>>>(x,    enc_w1, enc_b1, h1,   8192, 512,  128, 1, 0);
    sgemm128<<<dim3(4, 64),  t256>>>(h1,   enc_w2, enc_b2, h2,   8192, 512,  512, 1, 0);
    sgemm128<<<dim3(2, 64),  t256>>>(h2,   enc_w3, enc_b3, zOut, 8192, 256,  512, 0, 0);
    // GRU input projection (fp32 — c accuracy)
    sgemm128<<<dim3(12, 64), t256>>>(zOut, gru_wi, gru_bi, xi,   8192, 1536, 256, 0, 0);
    // GRU recurrence (reverted to R5-measured version)
    gru_kernel<<<128, 256>>>(gru_wh, gru_bhn, cOut);
    // prediction net on c[:, :-12] — tf32 tensor cores (loss-only path)
    tmma_kernel<0,0><<<dim3(4, 63), t256>>>(cOut, pred_w1, pred_b1, ph, 8000, 512, 512, 1, 1);
    tmma_kernel<0,0><<<dim3(2, 63), t256>>>(ph,   pred_w2, pred_b2, p,  8000, 256, 512, 0, 0);
    // normalize
    norm_p_kernel<<<1000, 256>>>();
    build_zn_kernel<<<1022, 256>>>(zOut);
    // fused Gram + epilogue — tf32 tensor cores
    tmma_kernel<1,1><<<dim3(64, 63), t256>>>(p, zn, nullptr, nullptr, NROWS, NCOLS, 256, 0, 0);
    // loss
    loss_kernel<<<1, 1024>>>(lOut);
}

// round 8
// speedup vs baseline: 1.2635x; 1.0310x over previous
#include <cuda_runtime.h>
#include <cuda_bf16.h>
#include <cstdint>

// ---------------- problem constants ----------------
#define NROWS 8000      // B*(T-K) rows of p
#define NCOLS 8176      // B*(T-1)  rows of zn

// ---------------- static scratch ----------------
__device__ float g_h1[8192 * 512];
__device__ float g_h2[8192 * 512];
__device__ float g_xi[8192 * 1536];
__device__ float g_ph[8000 * 512];
__device__ float g_p [8000 * 256];
__device__ float g_zn[8176 * 256];
__device__ float g_hbuf[2][8192];
__device__ float g_E[8000];
__device__ float g_low [8000 * 11];
__device__ float g_high[8000 * 11];
__device__ float g_diag[8000 * 12];
__device__ unsigned g_bar;

// ---------------- scoped sync helpers ----------------
__device__ __forceinline__ unsigned ld_acquire_gpu(const unsigned* p) {
    unsigned v;
    asm volatile("ld.acquire.gpu.u32 %0, [%1];" : "=r"(v) : "l"(p) : "memory");
    return v;
}
__device__ __forceinline__ void red_release_gpu(unsigned* p, unsigned v) {
    asm volatile("red.release.gpu.add.u32 [%0], %1;" :: "l"(p), "r"(v) : "memory");
}
__device__ __forceinline__ void stcg(float* p, float v) {
    asm volatile("st.global.cg.f32 [%0], %1;" :: "l"(p), "f"(v) : "memory");
}

// ---------------- async-copy / ldmatrix helpers ----------------
__device__ __forceinline__ void cp16(uint32_t dst, const void* src, unsigned szn) {
    asm volatile("cp.async.cg.shared.global [%0], [%1], 16, %2;"
                 :: "r"(dst), "l"(src), "r"(szn));
}
__device__ __forceinline__ void cp_commit() {
    asm volatile("cp.async.commit_group;" ::: "memory");
}
__device__ __forceinline__ void cp_wait0() {
    asm volatile("cp.async.wait_group 0;" ::: "memory");
}
__device__ __forceinline__ void ldsm_x4(uint32_t& r0, uint32_t& r1,
                                        uint32_t& r2, uint32_t& r3, uint32_t addr) {
    asm volatile("ldmatrix.sync.aligned.m8n8.x4.shared.b16 {%0,%1,%2,%3}, [%4];"
                 : "=r"(r0), "=r"(r1), "=r"(r2), "=r"(r3) : "r"(addr));
}

// ---------------- reset ----------------
__global__ void reset_kernel() {
    int idx = blockIdx.x * blockDim.x + threadIdx.x;
    int stride = gridDim.x * blockDim.x;
    for (int i = idx; i < 8000; i += stride) g_E[i] = 0.f;
    for (int i = idx; i < 8000 * 11; i += stride) { g_low[i] = 0.f; g_high[i] = 0.f; }
    for (int i = idx; i < 2 * 8192; i += stride) ((float*)g_hbuf)[i] = 0.f;
    if (idx == 0) g_bar = 0u;
}

// ---------------- fp32 SIMT SGEMM, double-buffered (enc chain + xi) ----------
__global__ __launch_bounds__(256) void sgemm128(
    const float* __restrict__ A, const float* __restrict__ W,
    const float* __restrict__ bias, float* __restrict__ C,
    int M, int N, int K, int doRelu, int rowmap)
{
    __shared__ float As[2][8][128];
    __shared__ float Bs[2][8][132];
    int tid = threadIdx.x;
    int bx = blockIdx.x, by = blockIdx.y;
    int tx = tid & 15, ty = tid >> 4;

    int arow = tid >> 1;
    int acol = (tid & 1) << 2;
    int grow = by * 128 + arow;
    bool aval = grow < M;
    long ar = grow;
    if (rowmap && aval) ar = grow + (grow / 500) * 12;
    const float* Ap = A + (size_t)ar * K + acol;

    int brow = tid >> 5;
    int bcol = (tid & 31) << 2;
    const float* Bp = W + (size_t)brow * N + (size_t)bx * 128 + bcol;

    float acc[8][8];
#pragma unroll
    for (int i = 0; i < 8; i++)
#pragma unroll
        for (int j = 0; j < 8; j++) acc[i][j] = 0.f;

    int tiles = K >> 3;
    {
        float4 av = aval ? *(const float4*)(Ap) : make_float4(0.f,0.f,0.f,0.f);
        float4 bv = *(const float4*)(Bp);
        As[0][acol + 0][arow] = av.x; As[0][acol + 1][arow] = av.y;
        As[0][acol + 2][arow] = av.z; As[0][acol + 3][arow] = av.w;
        *(float4*)&Bs[0][brow][bcol] = bv;
    }
    __syncthreads();

    for (int t = 0; t < tiles; t++) {
        int cur = t & 1;
        bool more = (t + 1) < tiles;
        float4 av2, bv2;
        if (more) {
            int k0 = (t + 1) << 3;
            av2 = aval ? *(const float4*)(Ap + k0) : make_float4(0.f,0.f,0.f,0.f);
            bv2 = *(const float4*)(Bp + (size_t)k0 * N);
        }
#pragma unroll
        for (int kk = 0; kk < 8; kk++) {
            float a[8], b[8];
            *(float4*)&a[0] = *(const float4*)&As[cur][kk][ty * 8];
            *(float4*)&a[4] = *(const float4*)&As[cur][kk][ty * 8 + 4];
            *(float4*)&b[0] = *(const float4*)&Bs[cur][kk][tx * 8];
            *(float4*)&b[4] = *(const float4*)&Bs[cur][kk][tx * 8 + 4];
#pragma unroll
            for (int i = 0; i < 8; i++)
#pragma unroll
                for (int j = 0; j < 8; j++) acc[i][j] = fmaf(a[i], b[j], acc[i][j]);
        }
        if (more) {
            int nxt = cur ^ 1;
            As[nxt][acol + 0][arow] = av2.x; As[nxt][acol + 1][arow] = av2.y;
            As[nxt][acol + 2][arow] = av2.z; As[nxt][acol + 3][arow] = av2.w;
            *(float4*)&Bs[nxt][brow][bcol] = bv2;
        }
        __syncthreads();
    }

    int cbase = bx * 128 + tx * 8;
#pragma unroll
    for (int i = 0; i < 8; i++) {
        int r = by * 128 + ty * 8 + i;
        if (r >= M) continue;
        float* Cp = C + (size_t)r * N + cbase;
#pragma unroll
        for (int j = 0; j < 8; j++) {
            float v = acc[i][j] + bias[cbase + j];
            if (doRelu) v = fmaxf(v, 0.f);
            Cp[j] = v;
        }
    }
}

// ---------------- mma helper ----------------
__device__ __forceinline__ void mma_tf32(
    float& c0, float& c1, float& c2, float& c3,
    uint32_t a0, uint32_t a1, uint32_t a2, uint32_t a3,
    uint32_t b0, uint32_t b1)
{
    asm volatile(
        "mma.sync.aligned.m16n8k8.row.col.f32.tf32.tf32.f32 "
        "{%0,%1,%2,%3}, {%4,%5,%6,%7}, {%8,%9}, {%0,%1,%2,%3};"
        : "+f"(c0), "+f"(c1), "+f"(c2), "+f"(c3)
        : "r"(a0), "r"(a1), "r"(a2), "r"(a3), "r"(b0), "r"(b1));
}

// ---------------- tf32 tensor GEMM v2: cp.async + ldmatrix (loss-only path) --
// CTA tile 128x128, BK=16, 8 warps (4m x 2n). Raw f32 staged (HMMA.TF32 reads
// top 19 bits = truncation rounding; loss-only). Frags via ldmatrix.x4.
// BMODE 0: B = weights [K][N] (register transpose staging)
// BMODE 1: B = [N][K] row-major (cp.async direct)
#define S2 20
#define TBUF (128 * S2)
template<int BMODE, int EPI>
__global__ __launch_bounds__(256) void tmma_kernel(
    const float* __restrict__ A, const float* __restrict__ B,
    const float* __restrict__ bias, float* __restrict__ C,
    int M, int N, int K, int doRelu, int rowmap)
{
    __shared__ __align__(16) uint32_t As[2][TBUF];
    __shared__ __align__(16) uint32_t Bs[2][TBUF];
    __shared__ float redsm[128];

    int tid = threadIdx.x;
    int bx = blockIdx.x, by = blockIdx.y;
    int wid = tid >> 5, lane = tid & 31;
    int wm = wid >> 1, wn = wid & 1;
    int g = lane >> 2, tg = lane & 3;
    int lm = lane >> 3, lr = lane & 7;

    if (EPI == 1 && tid < 128) redsm[tid] = 0.f;

    uint32_t as_base = (uint32_t)__cvta_generic_to_shared(&As[0][0]);
    uint32_t bs_base = (uint32_t)__cvta_generic_to_shared(&Bs[0][0]);

    // staging: 2 threads per row, 8 k each (two 16B chunks)
    int arow = tid >> 1;
    int akh = (tid & 1) << 3;
    int agrow = by * 128 + arow;
    bool aval = agrow < M;
    long ar = agrow;
    if (rowmap && aval) ar = agrow + (agrow / 500) * 12;
    const float* Ap = A + (size_t)ar * K + akh;
    unsigned aszn = aval ? 16u : 0u;
    uint32_t adst = (uint32_t)((arow * S2 + akh) << 2);

    // BMODE 1 B staging (cp.async)
    bool bval = (bx * 128 + arow) < N;
    const float* Bp_d = B + (size_t)(bx * 128 + arow) * K + akh;
    unsigned bszn = bval ? 16u : 0u;
    // BMODE 0 B staging (register transpose)
    int bn_t = tid & 127;
    int bkh_t = (tid >> 7) << 3;
    const float* Bp_t = B + (size_t)(bx * 128 + bn_t);
    float pbs[8];

    // ldmatrix lane bases (word offsets within a buffer)
    uint32_t aoff[2], boff[4];
#pragma unroll
    for (int mi = 0; mi < 2; mi++)
        aoff[mi] = (uint32_t)((wm * 32 + mi * 16 + (lm & 1) * 8 + lr) * S2 + (lm >> 1) * 4);
#pragma unroll
    for (int j = 0; j < 4; j++)
        boff[j] = (uint32_t)((wn * 64 + j * 16 + (lm >> 1) * 8 + lr) * S2 + (lm & 1) * 4);

    float acc[2][8][4];
#pragma unroll
    for (int mi = 0; mi < 2; mi++)
#pragma unroll
        for (int ni = 0; ni < 8; ni++)
#pragma unroll
            for (int q = 0; q < 4; q++) acc[mi][ni][q] = 0.f;

    int tiles = K >> 4;

    // prologue: issue tile 0
    {
        cp16(as_base + adst, Ap, aszn);
        cp16(as_base + adst + 16, Ap + 4, aszn);
        if (BMODE == 1) {
            cp16(bs_base + adst, Bp_d, bszn);
            cp16(bs_base + adst + 16, Bp_d + 4, bszn);
        } else {
#pragma unroll
            for (int j = 0; j < 8; j++) pbs[j] = Bp_t[(size_t)(bkh_t + j) * N];
        }
        cp_commit();
    }

    for (int t = 0; t < tiles; t++) {
        int cur = t & 1;
        cp_wait0();
        if (BMODE == 0) {
#pragma unroll
            for (int j = 0; j < 8; j++)
                Bs[cur][bn_t * S2 + bkh_t + j] = __float_as_uint(pbs[j]);
        }
        __syncthreads();

        bool more = (t + 1) < tiles;
        if (more) {
            int k0 = (t + 1) << 4;
            uint32_t bo = (uint32_t)((cur ^ 1) * (TBUF * 4));
            cp16(as_base + bo + adst, Ap + k0, aszn);
            cp16(as_base + bo + adst + 16, Ap + k0 + 4, aszn);
            if (BMODE == 1) {
                cp16(bs_base + bo + adst, Bp_d + k0, bszn);
                cp16(bs_base + bo + adst + 16, Bp_d + k0 + 4, bszn);
            } else {
#pragma unroll
                for (int j = 0; j < 8; j++)
                    pbs[j] = Bp_t[(size_t)(k0 + bkh_t + j) * N];
            }
            cp_commit();
        }

        uint32_t abase = as_base + (uint32_t)(cur * (TBUF * 4));
        uint32_t bbase = bs_base + (uint32_t)(cur * (TBUF * 4));
#pragma unroll
        for (int ks = 0; ks < 2; ks++) {
            int kb = ks * 8;
            uint32_t a[2][4];
            ldsm_x4(a[0][0], a[0][1], a[0][2], a[0][3], abase + ((aoff[0] + kb) << 2));
            ldsm_x4(a[1][0], a[1][1], a[1][2], a[1][3], abase + ((aoff[1] + kb) << 2));
            uint32_t bf[8][2];
#pragma unroll
            for (int j = 0; j < 4; j++)
                ldsm_x4(bf[2*j][0], bf[2*j][1], bf[2*j+1][0], bf[2*j+1][1],
                        bbase + ((boff[j] + kb) << 2));
#pragma unroll
            for (int ni = 0; ni < 8; ni++)
#pragma unroll
                for (int mi = 0; mi < 2; mi++)
                    mma_tf32(acc[mi][ni][0], acc[mi][ni][1],
                             acc[mi][ni][2], acc[mi][ni][3],
                             a[mi][0], a[mi][1], a[mi][2], a[mi][3],
                             bf[ni][0], bf[ni][1]);
        }
    }
    __syncthreads();

    if (EPI == 0) {
#pragma unroll
        for (int mi = 0; mi < 2; mi++) {
            int r0 = by * 128 + wm * 32 + mi * 16 + g;
#pragma unroll
            for (int ni = 0; ni < 8; ni++) {
                int cg = bx * 128 + wn * 64 + ni * 8 + tg * 2;
                float b0v = bias[cg], b1v = bias[cg + 1];
                float v0 = acc[mi][ni][0] + b0v;
                float v1 = acc[mi][ni][1] + b1v;
                float v2 = acc[mi][ni][2] + b0v;
                float v3 = acc[mi][ni][3] + b1v;
                if (doRelu) {
                    v0 = fmaxf(v0, 0.f); v1 = fmaxf(v1, 0.f);
                    v2 = fmaxf(v2, 0.f); v3 = fmaxf(v3, 0.f);
                }
                if (r0 < M)     *(float2*)&C[(size_t)r0 * N + cg]       = make_float2(v0, v1);
                if (r0 + 8 < M) *(float2*)&C[(size_t)(r0 + 8) * N + cg] = make_float2(v2, v3);
            }
        }
    } else {
        float rsum[2][2] = {{0.f,0.f},{0.f,0.f}};
#pragma unroll
        for (int ni = 0; ni < 8; ni++) {
            int cg0 = bx * 128 + wn * 64 + ni * 8 + tg * 2;
#pragma unroll
            for (int half = 0; half < 2; half++) {
                int cg = cg0 + half;
                if (cg >= NCOLS) continue;
                int cb = cg / 511;
                int mm = cg - cb * 511;
#pragma unroll
                for (int mi = 0; mi < 2; mi++) {
#pragma unroll
                    for (int rh = 0; rh < 2; rh++) {
                        int rg = by * 128 + wm * 32 + mi * 16 + rh * 8 + g;
                        if (rg >= NROWS) continue;
                        float s = acc[mi][ni][rh * 2 + half];
                        float e = __expf(s - 10.0f);
                        rsum[mi][rh] += e;
                        if (mm < 11) atomicAdd(&g_low[rg * 11 + mm], e);
                        else if (mm >= 500) atomicAdd(&g_high[rg * 11 + mm - 500], e);
                        int bi = rg / 500;
                        if (cb == bi) {
                            int dd = mm - (rg - bi * 500);
                            if (dd >= 0 && dd < 12) g_diag[rg * 12 + dd] = s;
                        }
                    }
                }
            }
        }
#pragma unroll
        for (int mi = 0; mi < 2; mi++)
#pragma unroll
            for (int rh = 0; rh < 2; rh++) {
                float v = rsum[mi][rh];
                v += __shfl_xor_sync(0xffffffffu, v, 1);
                v += __shfl_xor_sync(0xffffffffu, v, 2);
                if (tg == 0)
                    atomicAdd(&redsm[wm * 32 + mi * 16 + rh * 8 + g], v);
            }
        __syncthreads();
        if (tid < 128) {
            int rr = by * 128 + tid;
            if (rr < NROWS && redsm[tid] != 0.f) atomicAdd(&g_E[rr], redsm[tid]);
        }
    }
}

// ---------------- GRU persistent kernel (R5/R7-measured version) ----------
__global__ __launch_bounds__(256) void gru_kernel(
    const float* __restrict__ wh, const float* __restrict__ bhn,
    float* __restrict__ cOut)
{
    __shared__ float w_s[512 * 12];
    __shared__ float red[192 * 17];
    __shared__ float dot_s[192];
    __shared__ float bhn_s[4];
    int tid = threadIdx.x;
    int colBase = blockIdx.x * 4;

    for (int e = tid; e < 6144; e += 256) {
        int k = e / 12, r = e - k * 12;
        int g = r >> 2, cc = r & 3;
        w_s[e] = wh[(size_t)k * 1536 + g * 512 + colBase + cc];
    }
    if (tid < 4) bhn_s[tid] = bhn[colBase + tid];

    unsigned* barp; { unsigned* t_; asm("mov.u64 %0, g_bar;" : "=l"(t_)); barp = t_; }
    __syncthreads();

    int ks = tid >> 4;
    int row = tid & 15;
    int kbase = ks * 32;
    int grow2 = tid >> 2;
    int gcol = colBase + (tid & 3);

    for (int t = 0; t < 512; t++) {
        int rb = t & 1;
        const float* hb = g_hbuf[rb];

        float xr = 0.f, xu = 0.f, xn = 0.f, hold = 0.f;
        if (tid < 64) {
            size_t base = ((size_t)(grow2 << 9) + t) * 1536 + gcol;
            xr = __ldg(&g_xi[base]);
            xu = __ldg(&g_xi[base + 512]);
            xn = __ldg(&g_xi[base + 1024]);
            hold = __ldcg(&hb[gcol * 16 + grow2]);
        }

        float acc[12];
#pragma unroll
        for (int g = 0; g < 12; g++) acc[g] = 0.f;
#pragma unroll 8
        for (int j = 0; j < 32; j++) {
            int k = kbase + j;
            float hv = __ldcg(&hb[k * 16 + row]);
            const float4* w4 = (const float4*)&w_s[k * 12];
            float4 wr = w4[0], wu = w4[1], wn4 = w4[2];
            acc[0]  = fmaf(wr.x,  hv, acc[0]);
            acc[1]  = fmaf(wr.y,  hv, acc[1]);
            acc[2]  = fmaf(wr.z,  hv, acc[2]);
            acc[3]  = fmaf(wr.w,  hv, acc[3]);
            acc[4]  = fmaf(wu.x,  hv, acc[4]);
            acc[5]  = fmaf(wu.y,  hv, acc[5]);
            acc[6]  = fmaf(wu.z,  hv, acc[6]);
            acc[7]  = fmaf(wu.w,  hv, acc[7]);
            acc[8]  = fmaf(wn4.x, hv, acc[8]);
            acc[9]  = fmaf(wn4.y, hv, acc[9]);
            acc[10] = fmaf(wn4.z, hv, acc[10]);
            acc[11] = fmaf(wn4.w, hv, acc[11]);
        }
#pragma unroll
        for (int g = 0; g < 12; g++) red[(row * 12 + g) * 17 + ks] = acc[g];
        __syncthreads();

        if (tid < 192) {
            float v = 0.f;
#pragma unroll
            for (int s = 0; s < 16; s++) v += red[tid * 17 + s];
            dot_s[tid] = v;
        }
        __syncthreads();

        if (tid < 64) {
            int cc = tid & 3;
            float hr = dot_s[grow2 * 12 + cc];
            float hu = dot_s[grow2 * 12 + 4 + cc];
            float hn = dot_s[grow2 * 12 + 8 + cc];
            float r = 1.f / (1.f + __expf(-(xr + hr)));
            float u = 1.f / (1.f + __expf(-(xu + hu)));
            float n = tanhf(xn + r * (hn + bhn_s[cc]));
            float hnew = (1.f - u) * n + u * hold;
            stcg(&g_hbuf[rb ^ 1][gcol * 16 + grow2], hnew);
            cOut[((size_t)(grow2 << 9) + t) * 512 + gcol] = hnew;
        }

        __syncthreads();
        if (tid == 0) {
            red_release_gpu(barp, 1u);
            unsigned tgt = 128u * (unsigned)(t + 1);
            while (ld_acquire_gpu(barp) < tgt) { }
        }
        __syncthreads();
    }
}

// ---------------- row L2-normalize ----------------
__device__ __forceinline__ void norm_row(const float* src, float* dst, int lane, float extraScale) {
    float4 a = ((const float4*)src)[lane];
    float4 b = ((const float4*)src)[lane + 32];
    float ss = a.x*a.x + a.y*a.y + a.z*a.z + a.w*a.w
             + b.x*b.x + b.y*b.y + b.z*b.z + b.w*b.w;
#pragma unroll
    for (int o = 16; o > 0; o >>= 1) ss += __shfl_xor_sync(0xffffffffu, ss, o);
    float r = rsqrtf(ss);
    r = r * (1.5f - 0.5f * ss * r * r);
    r *= extraScale;
    a.x*=r; a.y*=r; a.z*=r; a.w*=r; b.x*=r; b.y*=r; b.z*=r; b.w*=r;
    ((float4*)dst)[lane] = a;
    ((float4*)dst)[lane + 32] = b;
}

__global__ void norm_p_kernel() {
    int w = (blockIdx.x * blockDim.x + threadIdx.x) >> 5;
    if (w >= NROWS) return;
    norm_row(g_p + (size_t)w * 256, g_p + (size_t)w * 256, threadIdx.x & 31, 10.0f);
}

__global__ void build_zn_kernel(const float* __restrict__ z) {
    int w = (blockIdx.x * blockDim.x + threadIdx.x) >> 5;
    if (w >= NCOLS) return;
    int b = w / 511, tt = w % 511;
    const float* src = z + (size_t)(b * 512 + tt + 1) * 256;
    norm_row(src, g_zn + (size_t)w * 256, threadIdx.x & 31, 1.0f);
}

// ---------------- loss finisher ----------------
__global__ void loss_kernel(float* __restrict__ out) {
    __shared__ float part[1024];
    int tid = threadIdx.x;
    float tot = 0.f;
    for (int i = tid; i < NROWS; i += 1024) {
        float E = g_E[i];
        float L[11], H[11];
        float low = 0.f, high = 0.f;
#pragma unroll
        for (int j = 0; j < 11; j++) {
            L[j] = g_low[i * 11 + j];
            H[j] = g_high[i * 11 + j];
            high += H[j];
        }
#pragma unroll
        for (int k = 1; k <= 12; k++) {
            if (k >= 2) { low += L[k - 2]; high -= H[k - 2]; }
            float window = E - low - high;
            tot += g_diag[i * 12 + (k - 1)] - (10.0f + logf(window));
        }
    }
    part[tid] = tot;
    __syncthreads();
    for (int s = 512; s > 0; s >>= 1) {
        if (tid < s) part[tid] += part[tid + s];
        __syncthreads();
    }
    if (tid == 0) out[0] = -part[0] / (12.0f * (float)NROWS);
}

// ---------------- driver ----------------
extern "C" void kernel_launch(void* const* d_in, const int* in_sizes, int n_in,
                              void* d_out, int out_size) {
    const float* x       = (const float*)d_in[0];
    const float* enc_w1  = (const float*)d_in[1];
    const float* enc_b1  = (const float*)d_in[2];
    const float* enc_w2  = (const float*)d_in[3];
    const float* enc_b2  = (const float*)d_in[4];
    const float* enc_w3  = (const float*)d_in[5];
    const float* enc_b3  = (const float*)d_in[6];
    const float* gru_wi  = (const float*)d_in[7];
    const float* gru_bi  = (const float*)d_in[8];
    const float* gru_wh  = (const float*)d_in[9];
    const float* gru_bhn = (const float*)d_in[10];
    const float* pred_w1 = (const float*)d_in[11];
    const float* pred_b1 = (const float*)d_in[12];
    const float* pred_w2 = (const float*)d_in[13];
    const float* pred_b2 = (const float*)d_in[14];

    float* out  = (float*)d_out;
    float* zOut = out;                       // [8192, 256]
    float* cOut = out + 2097152;             // [8192, 512]
    float* lOut = out + (out_size - 1);

    // Resolve true device addresses of scratch symbols (host-shadow trap!)
    float *h1, *h2, *xi, *ph, *p, *zn;
    cudaGetSymbolAddress((void**)&h1, g_h1);
    cudaGetSymbolAddress((void**)&h2, g_h2);
    cudaGetSymbolAddress((void**)&xi, g_xi);
    cudaGetSymbolAddress((void**)&ph, g_ph);
    cudaGetSymbolAddress((void**)&p,  g_p);
    cudaGetSymbolAddress((void**)&zn, g_zn);

    reset_kernel<<<64, 256>>>();

    dim3 t256(256);
    // encoder (fp32 — z exactness)
    sgemm128<<<dim3(4, 64),  t256>>>(x,    enc_w1, enc_b1, h1,   8192, 512,  128, 1, 0);
    sgemm128<<<dim3(4, 64),  t256>>>(h1,   enc_w2, enc_b2, h2,   8192, 512,  512, 1, 0);
    sgemm128<<<dim3(2, 64),  t256>>>(h2,   enc_w3, enc_b3, zOut, 8192, 256,  512, 0, 0);
    // GRU input projection (fp32 — c accuracy)
    sgemm128<<<dim3(12, 64), t256>>>(zOut, gru_wi, gru_bi, xi,   8192, 1536, 256, 0, 0);
    // GRU recurrence
    gru_kernel<<<128, 256>>>(gru_wh, gru_bhn, cOut);
    // prediction net on c[:, :-12] — tf32 tensor cores v2
    tmma_kernel<0,0><<<dim3(4, 63), t256>>>(cOut, pred_w1, pred_b1, ph, 8000, 512, 512, 1, 1);
    tmma_kernel<0,0><<<dim3(2, 63), t256>>>(ph,   pred_w2, pred_b2, p,  8000, 256, 512, 0, 0);
    // normalize
    norm_p_kernel<<<1000, 256>>>();
    build_zn_kernel<<<1022, 256>>>(zOut);
    // fused Gram + epilogue — tf32 tensor cores v2 (cp.async + ldmatrix)
    tmma_kernel<1,1><<<dim3(64, 63), t256>>>(p, zn, nullptr, nullptr, NROWS, NCOLS, 256, 0, 0);
    // loss
    loss_kernel<<<1, 1024>>>(lOut);
}

// round 10
// speedup vs baseline: 1.5936x; 1.2613x over previous
#include <cuda_runtime.h>
#include <cuda_bf16.h>
#include <cstdint>

// ---------------- problem constants ----------------
#define NROWS 8000      // B*(T-K) rows of p
#define NCOLS 8176      // B*(T-1)  rows of zn

// ---------------- static scratch ----------------
__device__ float g_h1[8192 * 512];
__device__ float g_h2[8192 * 512];
__device__ float g_xi[8192 * 1536];
__device__ float g_ph[8000 * 512];
__device__ float g_p [8000 * 256];
__device__ __nv_bfloat16 g_pb [8064 * 256];   // p-hat * 10, bf16 (63*128 rows)
__device__ __nv_bfloat16 g_znb[8192 * 256];   // zn-hat, bf16 (64*128 rows)
__device__ float g_hbuf[2][8192];
__device__ float g_E[8000];
__device__ float g_low [8000 * 11];
__device__ float g_high[8000 * 11];
__device__ float g_diag[8000 * 12];
__device__ unsigned g_bar;

// ---------------- scoped sync helpers ----------------
__device__ __forceinline__ unsigned ld_acquire_gpu(const unsigned* p) {
    unsigned v;
    asm volatile("ld.acquire.gpu.u32 %0, [%1];" : "=r"(v) : "l"(p) : "memory");
    return v;
}
__device__ __forceinline__ void red_release_gpu(unsigned* p, unsigned v) {
    asm volatile("red.release.gpu.add.u32 [%0], %1;" :: "l"(p), "r"(v) : "memory");
}
__device__ __forceinline__ void stcg(float* p, float v) {
    asm volatile("st.global.cg.f32 [%0], %1;" :: "l"(p), "f"(v) : "memory");
}

// ---------------- async-copy / ldmatrix helpers ----------------
__device__ __forceinline__ void cp16(uint32_t dst, const void* src, unsigned szn) {
    asm volatile("cp.async.cg.shared.global [%0], [%1], 16, %2;"
                 :: "r"(dst), "l"(src), "r"(szn));
}
__device__ __forceinline__ void cp_commit() {
    asm volatile("cp.async.commit_group;" ::: "memory");
}
__device__ __forceinline__ void cp_wait0() {
    asm volatile("cp.async.wait_group 0;" ::: "memory");
}
__device__ __forceinline__ void ldsm_x4(uint32_t& r0, uint32_t& r1,
                                        uint32_t& r2, uint32_t& r3, uint32_t addr) {
    asm volatile("ldmatrix.sync.aligned.m8n8.x4.shared.b16 {%0,%1,%2,%3}, [%4];"
                 : "=r"(r0), "=r"(r1), "=r"(r2), "=r"(r3) : "r"(addr));
}

// ---------------- reset ----------------
__global__ void reset_kernel() {
    int idx = blockIdx.x * blockDim.x + threadIdx.x;
    int stride = gridDim.x * blockDim.x;
    for (int i = idx; i < 8000; i += stride) g_E[i] = 0.f;
    for (int i = idx; i < 8000 * 11; i += stride) { g_low[i] = 0.f; g_high[i] = 0.f; }
    for (int i = idx; i < 2 * 8192; i += stride) ((float*)g_hbuf)[i] = 0.f;
    if (idx == 0) g_bar = 0u;
}

// ---------------- fp32 SIMT SGEMM, double-buffered (enc chain + xi) ----------
__global__ __launch_bounds__(256) void sgemm128(
    const float* __restrict__ A, const float* __restrict__ W,
    const float* __restrict__ bias, float* __restrict__ C,
    int M, int N, int K, int doRelu, int rowmap)
{
    __shared__ float As[2][8][128];
    __shared__ float Bs[2][8][132];
    int tid = threadIdx.x;
    int bx = blockIdx.x, by = blockIdx.y;
    int tx = tid & 15, ty = tid >> 4;

    int arow = tid >> 1;
    int acol = (tid & 1) << 2;
    int grow = by * 128 + arow;
    bool aval = grow < M;
    long ar = grow;
    if (rowmap && aval) ar = grow + (grow / 500) * 12;
    const float* Ap = A + (size_t)ar * K + acol;

    int brow = tid >> 5;
    int bcol = (tid & 31) << 2;
    const float* Bp = W + (size_t)brow * N + (size_t)bx * 128 + bcol;

    float acc[8][8];
#pragma unroll
    for (int i = 0; i < 8; i++)
#pragma unroll
        for (int j = 0; j < 8; j++) acc[i][j] = 0.f;

    int tiles = K >> 3;
    {
        float4 av = aval ? *(const float4*)(Ap) : make_float4(0.f,0.f,0.f,0.f);
        float4 bv = *(const float4*)(Bp);
        As[0][acol + 0][arow] = av.x; As[0][acol + 1][arow] = av.y;
        As[0][acol + 2][arow] = av.z; As[0][acol + 3][arow] = av.w;
        *(float4*)&Bs[0][brow][bcol] = bv;
    }
    __syncthreads();

    for (int t = 0; t < tiles; t++) {
        int cur = t & 1;
        bool more = (t + 1) < tiles;
        float4 av2, bv2;
        if (more) {
            int k0 = (t + 1) << 3;
            av2 = aval ? *(const float4*)(Ap + k0) : make_float4(0.f,0.f,0.f,0.f);
            bv2 = *(const float4*)(Bp + (size_t)k0 * N);
        }
#pragma unroll
        for (int kk = 0; kk < 8; kk++) {
            float a[8], b[8];
            *(float4*)&a[0] = *(const float4*)&As[cur][kk][ty * 8];
            *(float4*)&a[4] = *(const float4*)&As[cur][kk][ty * 8 + 4];
            *(float4*)&b[0] = *(const float4*)&Bs[cur][kk][tx * 8];
            *(float4*)&b[4] = *(const float4*)&Bs[cur][kk][tx * 8 + 4];
#pragma unroll
            for (int i = 0; i < 8; i++)
#pragma unroll
                for (int j = 0; j < 8; j++) acc[i][j] = fmaf(a[i], b[j], acc[i][j]);
        }
        if (more) {
            int nxt = cur ^ 1;
            As[nxt][acol + 0][arow] = av2.x; As[nxt][acol + 1][arow] = av2.y;
            As[nxt][acol + 2][arow] = av2.z; As[nxt][acol + 3][arow] = av2.w;
            *(float4*)&Bs[nxt][brow][bcol] = bv2;
        }
        __syncthreads();
    }

    int cbase = bx * 128 + tx * 8;
#pragma unroll
    for (int i = 0; i < 8; i++) {
        int r = by * 128 + ty * 8 + i;
        if (r >= M) continue;
        float* Cp = C + (size_t)r * N + cbase;
#pragma unroll
        for (int j = 0; j < 8; j++) {
            float v = acc[i][j] + bias[cbase + j];
            if (doRelu) v = fmaxf(v, 0.f);
            Cp[j] = v;
        }
    }
}

// ---------------- mma helpers ----------------
__device__ __forceinline__ void mma_tf32(
    float& c0, float& c1, float& c2, float& c3,
    uint32_t a0, uint32_t a1, uint32_t a2, uint32_t a3,
    uint32_t b0, uint32_t b1)
{
    asm volatile(
        "mma.sync.aligned.m16n8k8.row.col.f32.tf32.tf32.f32 "
        "{%0,%1,%2,%3}, {%4,%5,%6,%7}, {%8,%9}, {%0,%1,%2,%3};"
        : "+f"(c0), "+f"(c1), "+f"(c2), "+f"(c3)
        : "r"(a0), "r"(a1), "r"(a2), "r"(a3), "r"(b0), "r"(b1));
}
__device__ __forceinline__ void mma_bf16(
    float& c0, float& c1, float& c2, float& c3,
    uint32_t a0, uint32_t a1, uint32_t a2, uint32_t a3,
    uint32_t b0, uint32_t b1)
{
    asm volatile(
        "mma.sync.aligned.m16n8k16.row.col.f32.bf16.bf16.f32 "
        "{%0,%1,%2,%3}, {%4,%5,%6,%7}, {%8,%9}, {%0,%1,%2,%3};"
        : "+f"(c0), "+f"(c1), "+f"(c2), "+f"(c3)
        : "r"(a0), "r"(a1), "r"(a2), "r"(a3), "r"(b0), "r"(b1));
}

// ---------------- tf32 mma.sync GEMM (pred1/pred2) ----------------
#define S2 20
#define TBUF (128 * S2)
__global__ __launch_bounds__(256) void tmma_kernel(
    const float* __restrict__ A, const float* __restrict__ B,
    const float* __restrict__ bias, float* __restrict__ C,
    int M, int N, int K, int doRelu, int rowmap)
{
    __shared__ __align__(16) uint32_t As[2][TBUF];
    __shared__ __align__(16) uint32_t Bs[2][TBUF];

    int tid = threadIdx.x;
    int bx = blockIdx.x, by = blockIdx.y;
    int wid = tid >> 5, lane = tid & 31;
    int wm = wid >> 1, wn = wid & 1;
    int g = lane >> 2, tg = lane & 3;
    int lm = lane >> 3, lr = lane & 7;

    uint32_t as_base = (uint32_t)__cvta_generic_to_shared(&As[0][0]);
    uint32_t bs_base = (uint32_t)__cvta_generic_to_shared(&Bs[0][0]);

    int arow = tid >> 1;
    int akh = (tid & 1) << 3;
    int agrow = by * 128 + arow;
    bool aval = agrow < M;
    long ar = agrow;
    if (rowmap && aval) ar = agrow + (agrow / 500) * 12;
    const float* Ap = A + (size_t)ar * K + akh;
    unsigned aszn = aval ? 16u : 0u;
    uint32_t adst = (uint32_t)((arow * S2 + akh) << 2);

    int bn_t = tid & 127;
    int bkh_t = (tid >> 7) << 3;
    const float* Bp_t = B + (size_t)(bx * 128 + bn_t);
    float pbs[8];

    uint32_t aoff[2], boff[4];
#pragma unroll
    for (int mi = 0; mi < 2; mi++)
        aoff[mi] = (uint32_t)((wm * 32 + mi * 16 + (lm & 1) * 8 + lr) * S2 + (lm >> 1) * 4);
#pragma unroll
    for (int j = 0; j < 4; j++)
        boff[j] = (uint32_t)((wn * 64 + j * 16 + (lm >> 1) * 8 + lr) * S2 + (lm & 1) * 4);

    float acc[2][8][4];
#pragma unroll
    for (int mi = 0; mi < 2; mi++)
#pragma unroll
        for (int ni = 0; ni < 8; ni++)
#pragma unroll
            for (int q = 0; q < 4; q++) acc[mi][ni][q] = 0.f;

    int tiles = K >> 4;
    {
        cp16(as_base + adst, Ap, aszn);
        cp16(as_base + adst + 16, Ap + 4, aszn);
#pragma unroll
        for (int j = 0; j < 8; j++) pbs[j] = Bp_t[(size_t)(bkh_t + j) * N];
        cp_commit();
    }

    for (int t = 0; t < tiles; t++) {
        int cur = t & 1;
        cp_wait0();
#pragma unroll
        for (int j = 0; j < 8; j++)
            Bs[cur][bn_t * S2 + bkh_t + j] = __float_as_uint(pbs[j]);
        __syncthreads();

        bool more = (t + 1) < tiles;
        if (more) {
            int k0 = (t + 1) << 4;
            uint32_t bo = (uint32_t)((cur ^ 1) * (TBUF * 4));
            cp16(as_base + bo + adst, Ap + k0, aszn);
            cp16(as_base + bo + adst + 16, Ap + k0 + 4, aszn);
#pragma unroll
            for (int j = 0; j < 8; j++)
                pbs[j] = Bp_t[(size_t)(k0 + bkh_t + j) * N];
            cp_commit();
        }

        uint32_t abase = as_base + (uint32_t)(cur * (TBUF * 4));
        uint32_t bbase = bs_base + (uint32_t)(cur * (TBUF * 4));
#pragma unroll
        for (int ks = 0; ks < 2; ks++) {
            int kb = ks * 8;
            uint32_t a[2][4];
            ldsm_x4(a[0][0], a[0][1], a[0][2], a[0][3], abase + ((aoff[0] + kb) << 2));
            ldsm_x4(a[1][0], a[1][1], a[1][2], a[1][3], abase + ((aoff[1] + kb) << 2));
            uint32_t bf[8][2];
#pragma unroll
            for (int j = 0; j < 4; j++)
                ldsm_x4(bf[2*j][0], bf[2*j][1], bf[2*j+1][0], bf[2*j+1][1],
                        bbase + ((boff[j] + kb) << 2));
#pragma unroll
            for (int ni = 0; ni < 8; ni++)
#pragma unroll
                for (int mi = 0; mi < 2; mi++)
                    mma_tf32(acc[mi][ni][0], acc[mi][ni][1],
                             acc[mi][ni][2], acc[mi][ni][3],
                             a[mi][0], a[mi][1], a[mi][2], a[mi][3],
                             bf[ni][0], bf[ni][1]);
        }
    }
    __syncthreads();

#pragma unroll
    for (int mi = 0; mi < 2; mi++) {
        int r0 = by * 128 + wm * 32 + mi * 16 + g;
#pragma unroll
        for (int ni = 0; ni < 8; ni++) {
            int cg = bx * 128 + wn * 64 + ni * 8 + tg * 2;
            float b0v = bias[cg], b1v = bias[cg + 1];
            float v0 = acc[mi][ni][0] + b0v;
            float v1 = acc[mi][ni][1] + b1v;
            float v2 = acc[mi][ni][2] + b0v;
            float v3 = acc[mi][ni][3] + b1v;
            if (doRelu) {
                v0 = fmaxf(v0, 0.f); v1 = fmaxf(v1, 0.f);
                v2 = fmaxf(v2, 0.f); v3 = fmaxf(v3, 0.f);
            }
            if (r0 < M)     *(float2*)&C[(size_t)r0 * N + cg]       = make_float2(v0, v1);
            if (r0 + 8 < M) *(float2*)&C[(size_t)(r0 + 8) * N + cg] = make_float2(v2, v3);
        }
    }
}

// ---------------- bf16 Gram kernel: m16n8k16 + fused epilogue ----------------
// s = (10*p-hat) . zn-hat, via bf16 HMMA (2x K per instr vs tf32).
// A = g_pb [8064][256], B = g_znb [8192][256], both K-major bf16.
// Row stride in smem: 80 bytes (40 halves) -> ldmatrix conflict-free.
#define GBY 10240   // bytes per buffer (128 rows * 80 B)
__global__ __launch_bounds__(256) void gram_bf16_kernel() {
    __shared__ __align__(16) char Asm[2][GBY];
    __shared__ __align__(16) char Bsm[2][GBY];
    __shared__ float redsm[128];

    int tid = threadIdx.x;
    int bx = blockIdx.x, by = blockIdx.y;
    int wid = tid >> 5, lane = tid & 31;
    int wm = wid >> 1, wn = wid & 1;
    int g = lane >> 2, tg = lane & 3;

    if (tid < 128) redsm[tid] = 0.f;

    uint32_t as_base = (uint32_t)__cvta_generic_to_shared(&Asm[0][0]);
    uint32_t bs_base = (uint32_t)__cvta_generic_to_shared(&Bsm[0][0]);

    int arow = tid >> 1;
    int ach = tid & 1;              // 2 threads per row, 32B each
    int rga = by * 128 + arow;
    unsigned aszn = (rga < NROWS) ? 16u : 0u;
    const __nv_bfloat16* Ap = g_pb + (size_t)rga * 256 + ach * 16;
    int ngb = bx * 128 + arow;
    unsigned bszn = (ngb < NCOLS) ? 16u : 0u;
    const __nv_bfloat16* Bp = g_znb + (size_t)ngb * 256 + ach * 16;
    uint32_t dst = (uint32_t)(arow * 80 + ach * 32);

    // ldmatrix lane address terms (bytes)
    uint32_t a_lane = (lane & 7) * 80 + ((lane >> 3) & 1) * 640 + ((lane >> 4) & 1) * 16;
    uint32_t b_lane = (lane & 7) * 80 + ((lane >> 4) & 1) * 640 + ((lane >> 3) & 1) * 16;

    float acc[2][8][4];
#pragma unroll
    for (int mi = 0; mi < 2; mi++)
#pragma unroll
        for (int ni = 0; ni < 8; ni++)
#pragma unroll
            for (int q = 0; q < 4; q++) acc[mi][ni][q] = 0.f;

    // prologue: tile 0 (k halves [0,32))
    cp16(as_base + dst, Ap, aszn);
    cp16(as_base + dst + 16, Ap + 8, aszn);
    cp16(bs_base + dst, Bp, bszn);
    cp16(bs_base + dst + 16, Bp + 8, bszn);
    cp_commit();

    for (int t = 0; t < 8; t++) {          // 8 tiles of 32 halves
        int cur = t & 1;
        cp_wait0();
        __syncthreads();

        if (t + 1 < 8) {
            int kh = (t + 1) * 32;          // halves
            uint32_t bo = (uint32_t)((cur ^ 1) * GBY);
            cp16(as_base + bo + dst, Ap + kh, aszn);
            cp16(as_base + bo + dst + 16, Ap + kh + 8, aszn);
            cp16(bs_base + bo + dst, Bp + kh, bszn);
            cp16(bs_base + bo + dst + 16, Bp + kh + 8, bszn);
            cp_commit();
        }

        uint32_t ab = as_base + (uint32_t)(cur * GBY);
        uint32_t bb = bs_base + (uint32_t)(cur * GBY);
#pragma unroll
        for (int ks = 0; ks < 2; ks++) {    // two k16 steps
            uint32_t kbyte = (uint32_t)(ks * 32);
            uint32_t a[2][4];
            ldsm_x4(a[0][0], a[0][1], a[0][2], a[0][3],
                    ab + (uint32_t)(wm * 32) * 80 + kbyte + a_lane);
            ldsm_x4(a[1][0], a[1][1], a[1][2], a[1][3],
                    ab + (uint32_t)(wm * 32 + 16) * 80 + kbyte + a_lane);
            uint32_t bf[8][2];
#pragma unroll
            for (int j = 0; j < 4; j++)
                ldsm_x4(bf[2*j][0], bf[2*j][1], bf[2*j+1][0], bf[2*j+1][1],
                        bb + (uint32_t)(wn * 64 + j * 16) * 80 + kbyte + b_lane);
#pragma unroll
            for (int ni = 0; ni < 8; ni++)
#pragma unroll
                for (int mi = 0; mi < 2; mi++)
                    mma_bf16(acc[mi][ni][0], acc[mi][ni][1],
                             acc[mi][ni][2], acc[mi][ni][3],
                             a[mi][0], a[mi][1], a[mi][2], a[mi][3],
                             bf[ni][0], bf[ni][1]);
        }
        if (t + 1 < 8) __syncthreads();     // protect cur buffer until refill target differs
    }

    // epilogue: exp / E / boundary / diag
    float rsum[2][2] = {{0.f,0.f},{0.f,0.f}};
#pragma unroll
    for (int ni = 0; ni < 8; ni++) {
        int cg0 = bx * 128 + wn * 64 + ni * 8 + tg * 2;
#pragma unroll
        for (int half = 0; half < 2; half++) {
            int cg = cg0 + half;
            if (cg >= NCOLS) continue;
            int cb = cg / 511;
            int mm = cg - cb * 511;
#pragma unroll
            for (int mi = 0; mi < 2; mi++) {
#pragma unroll
                for (int rh = 0; rh < 2; rh++) {
                    int rg = by * 128 + wm * 32 + mi * 16 + rh * 8 + g;
                    if (rg >= NROWS) continue;
                    float s = acc[mi][ni][rh * 2 + half];
                    float e = __expf(s - 10.0f);
                    rsum[mi][rh] += e;
                    if (mm < 11) atomicAdd(&g_low[rg * 11 + mm], e);
                    else if (mm >= 500) atomicAdd(&g_high[rg * 11 + mm - 500], e);
                    int bi = rg / 500;
                    if (cb == bi) {
                        int dd = mm - (rg - bi * 500);
                        if (dd >= 0 && dd < 12) g_diag[rg * 12 + dd] = s;
                    }
                }
            }
        }
    }
#pragma unroll
    for (int mi = 0; mi < 2; mi++)
#pragma unroll
        for (int rh = 0; rh < 2; rh++) {
            float v = rsum[mi][rh];
            v += __shfl_xor_sync(0xffffffffu, v, 1);
            v += __shfl_xor_sync(0xffffffffu, v, 2);
            if (tg == 0)
                atomicAdd(&redsm[wm * 32 + mi * 16 + rh * 8 + g], v);
        }
    __syncthreads();
    if (tid < 128) {
        int rr = by * 128 + tid;
        if (rr < NROWS && redsm[tid] != 0.f) atomicAdd(&g_E[rr], redsm[tid]);
    }
}

// ---------------- GRU persistent kernel (R8 + h-prefetch) ----------
__global__ __launch_bounds__(256) void gru_kernel(
    const float* __restrict__ wh, const float* __restrict__ bhn,
    float* __restrict__ cOut)
{
    __shared__ float w_s[512 * 12];
    __shared__ float red[192 * 17];
    __shared__ float dot_s[192];
    __shared__ float bhn_s[4];
    int tid = threadIdx.x;
    int colBase = blockIdx.x * 4;

    for (int e = tid; e < 6144; e += 256) {
        int k = e / 12, r = e - k * 12;
        int g = r >> 2, cc = r & 3;
        w_s[e] = wh[(size_t)k * 1536 + g * 512 + colBase + cc];
    }
    if (tid < 4) bhn_s[tid] = bhn[colBase + tid];

    unsigned* barp; { unsigned* t_; asm("mov.u64 %0, g_bar;" : "=l"(t_)); barp = t_; }
    __syncthreads();

    int ks = tid >> 4;
    int row = tid & 15;
    int kbase = ks * 32;
    int grow2 = tid >> 2;
    int gcol = colBase + (tid & 3);

    for (int t = 0; t < 512; t++) {
        int rb = t & 1;
        const float* hb = g_hbuf[rb];

        float xr = 0.f, xu = 0.f, xn = 0.f, hold = 0.f;
        if (tid < 64) {
            size_t base = ((size_t)(grow2 << 9) + t) * 1536 + gcol;
            xr = __ldg(&g_xi[base]);
            xu = __ldg(&g_xi[base + 512]);
            xn = __ldg(&g_xi[base + 1024]);
            hold = __ldcg(&hb[gcol * 16 + grow2]);
        }

        // prefetch ALL 32 h values (MLP=32) before the FMA chain
        float hv[32];
#pragma unroll
        for (int j = 0; j < 32; j++)
            hv[j] = __ldcg(&hb[(kbase + j) * 16 + row]);

        float acc[12];
#pragma unroll
        for (int g = 0; g < 12; g++) acc[g] = 0.f;
#pragma unroll
        for (int j = 0; j < 32; j++) {
            int k = kbase + j;
            const float4* w4 = (const float4*)&w_s[k * 12];
            float4 wr = w4[0], wu = w4[1], wn4 = w4[2];
            float h = hv[j];
            acc[0]  = fmaf(wr.x,  h, acc[0]);
            acc[1]  = fmaf(wr.y,  h, acc[1]);
            acc[2]  = fmaf(wr.z,  h, acc[2]);
            acc[3]  = fmaf(wr.w,  h, acc[3]);
            acc[4]  = fmaf(wu.x,  h, acc[4]);
            acc[5]  = fmaf(wu.y,  h, acc[5]);
            acc[6]  = fmaf(wu.z,  h, acc[6]);
            acc[7]  = fmaf(wu.w,  h, acc[7]);
            acc[8]  = fmaf(wn4.x, h, acc[8]);
            acc[9]  = fmaf(wn4.y, h, acc[9]);
            acc[10] = fmaf(wn4.z, h, acc[10]);
            acc[11] = fmaf(wn4.w, h, acc[11]);
        }
#pragma unroll
        for (int g = 0; g < 12; g++) red[(row * 12 + g) * 17 + ks] = acc[g];
        __syncthreads();

        if (tid < 192) {
            float v = 0.f;
#pragma unroll
            for (int s = 0; s < 16; s++) v += red[tid * 17 + s];
            dot_s[tid] = v;
        }
        __syncthreads();

        if (tid < 64) {
            int cc = tid & 3;
            float hr = dot_s[grow2 * 12 + cc];
            float hu = dot_s[grow2 * 12 + 4 + cc];
            float hn = dot_s[grow2 * 12 + 8 + cc];
            float r = 1.f / (1.f + __expf(-(xr + hr)));
            float u = 1.f / (1.f + __expf(-(xu + hu)));
            float n = tanhf(xn + r * (hn + bhn_s[cc]));
            float hnew = (1.f - u) * n + u * hold;
            stcg(&g_hbuf[rb ^ 1][gcol * 16 + grow2], hnew);
            cOut[((size_t)(grow2 << 9) + t) * 512 + gcol] = hnew;
        }

        __syncthreads();
        if (tid == 0) {
            red_release_gpu(barp, 1u);
            unsigned tgt = 128u * (unsigned)(t + 1);
            while (ld_acquire_gpu(barp) < tgt) { }
        }
        __syncthreads();
    }
}

// ---------------- row L2-normalize -> bf16 ----------------
__device__ __forceinline__ uint32_t pk2(float a, float b) {
    __nv_bfloat162 h = __floats2bfloat162_rn(a, b);
    return *(uint32_t*)&h;
}
__device__ __forceinline__ void norm_row_bf16(const float* src, __nv_bfloat16* dst,
                                              int lane, float extraScale) {
    float4 a = ((const float4*)src)[lane];
    float4 b = ((const float4*)src)[lane + 32];
    float ss = a.x*a.x + a.y*a.y + a.z*a.z + a.w*a.w
             + b.x*b.x + b.y*b.y + b.z*b.z + b.w*b.w;
#pragma unroll
    for (int o = 16; o > 0; o >>= 1) ss += __shfl_xor_sync(0xffffffffu, ss, o);
    float r = rsqrtf(ss);
    r = r * (1.5f - 0.5f * ss * r * r);
    r *= extraScale;
    uint2 lo, hi;
    lo.x = pk2(a.x * r, a.y * r); lo.y = pk2(a.z * r, a.w * r);
    hi.x = pk2(b.x * r, b.y * r); hi.y = pk2(b.z * r, b.w * r);
    ((uint2*)dst)[lane] = lo;
    ((uint2*)dst)[lane + 32] = hi;
}

__global__ void norm_p_kernel() {
    int w = (blockIdx.x * blockDim.x + threadIdx.x) >> 5;
    if (w >= NROWS) return;
    // fold 1/TEMP into p-hat
    norm_row_bf16(g_p + (size_t)w * 256, g_pb + (size_t)w * 256, threadIdx.x & 31, 10.0f);
}

__global__ void build_zn_kernel(const float* __restrict__ z) {
    int w = (blockIdx.x * blockDim.x + threadIdx.x) >> 5;
    if (w >= NCOLS) return;
    int b = w / 511, tt = w % 511;
    const float* src = z + (size_t)(b * 512 + tt + 1) * 256;
    norm_row_bf16(src, g_znb + (size_t)w * 256, threadIdx.x & 31, 1.0f);
}

// ---------------- loss finisher ----------------
__global__ void loss_kernel(float* __restrict__ out) {
    __shared__ float part[1024];
    int tid = threadIdx.x;
    float tot = 0.f;
    for (int i = tid; i < NROWS; i += 1024) {
        float E = g_E[i];
        float L[11], H[11];
        float low = 0.f, high = 0.f;
#pragma unroll
        for (int j = 0; j < 11; j++) {
            L[j] = g_low[i * 11 + j];
            H[j] = g_high[i * 11 + j];
            high += H[j];
        }
#pragma unroll
        for (int k = 1; k <= 12; k++) {
            if (k >= 2) { low += L[k - 2]; high -= H[k - 2]; }
            float window = E - low - high;
            tot += g_diag[i * 12 + (k - 1)] - (10.0f + logf(window));
        }
    }
    part[tid] = tot;
    __syncthreads();
    for (int s = 512; s > 0; s >>= 1) {
        if (tid < s) part[tid] += part[tid + s];
        __syncthreads();
    }
    if (tid == 0) out[0] = -part[0] / (12.0f * (float)NROWS);
}

// ---------------- driver ----------------
extern "C" void kernel_launch(void* const* d_in, const int* in_sizes, int n_in,
                              void* d_out, int out_size) {
    const float* x       = (const float*)d_in[0];
    const float* enc_w1  = (const float*)d_in[1];
    const float* enc_b1  = (const float*)d_in[2];
    const float* enc_w2  = (const float*)d_in[3];
    const float* enc_b2  = (const float*)d_in[4];
    const float* enc_w3  = (const float*)d_in[5];
    const float* enc_b3  = (const float*)d_in[6];
    const float* gru_wi  = (const float*)d_in[7];
    const float* gru_bi  = (const float*)d_in[8];
    const float* gru_wh  = (const float*)d_in[9];
    const float* gru_bhn = (const float*)d_in[10];
    const float* pred_w1 = (const float*)d_in[11];
    const float* pred_b1 = (const float*)d_in[12];
    const float* pred_w2 = (const float*)d_in[13];
    const float* pred_b2 = (const float*)d_in[14];

    float* out  = (float*)d_out;
    float* zOut = out;                       // [8192, 256]
    float* cOut = out + 2097152;             // [8192, 512]
    float* lOut = out + (out_size - 1);

    // Resolve true device addresses of scratch symbols (host-shadow trap!)
    float *h1, *h2, *xi, *ph, *p;
    cudaGetSymbolAddress((void**)&h1, g_h1);
    cudaGetSymbolAddress((void**)&h2, g_h2);
    cudaGetSymbolAddress((void**)&xi, g_xi);
    cudaGetSymbolAddress((void**)&ph, g_ph);
    cudaGetSymbolAddress((void**)&p,  g_p);

    reset_kernel<<<64, 256>>>();

    dim3 t256(256);
    // encoder (fp32 — z exactness)
    sgemm128<<<dim3(4, 64),  t256>>>(x,    enc_w1, enc_b1, h1,   8192, 512,  128, 1, 0);
    sgemm128<<<dim3(4, 64),  t256>>>(h1,   enc_w2, enc_b2, h2,   8192, 512,  512, 1, 0);
    sgemm128<<<dim3(2, 64),  t256>>>(h2,   enc_w3, enc_b3, zOut, 8192, 256,  512, 0, 0);
    // GRU input projection (fp32 — c accuracy)
    sgemm128<<<dim3(12, 64), t256>>>(zOut, gru_wi, gru_bi, xi,   8192, 1536, 256, 0, 0);
    // GRU recurrence (h-prefetch)
    gru_kernel<<<128, 256>>>(gru_wh, gru_bhn, cOut);
    // prediction net on c[:, :-12] — tf32 mma.sync (proven)
    tmma_kernel<<<dim3(4, 63), t256>>>(cOut, pred_w1, pred_b1, ph, 8000, 512, 512, 1, 1);
    tmma_kernel<<<dim3(2, 63), t256>>>(ph,   pred_w2, pred_b2, p,  8000, 256, 512, 0, 0);
    // normalize -> bf16
    norm_p_kernel<<<1000, 256>>>();
    build_zn_kernel<<<1022, 256>>>(zOut);
    // fused Gram + epilogue — bf16 m16n8k16
    gram_bf16_kernel<<<dim3(64, 63), t256>>>();
    // loss
    loss_kernel<<<1, 1024>>>(lOut);
}